// round 1
// baseline (speedup 1.0000x reference)
#include <cuda_runtime.h>
#include <cuda_bf16.h>
#include <math.h>

// Problem constants (Attention_146028888650)
#define BATCH 2
#define SEQ   2048
#define DIM   768
#define NHEAD 12
#define HDIM  64
#define KVW   128           // 2*HDIM
#define MROWS (BATCH*SEQ)   // 4096
#define ATT_SCALE 0.125f    // 64^-0.5

// Scratch (device globals — no runtime allocation allowed)
__device__ float g_Q [(size_t)MROWS * DIM];   // x @ Wq   -> [B*N, 768] (== B,N,H,D layout)
__device__ float g_KV[(size_t)MROWS * KVW];   // x @ Wkv  -> [B*N, 128]; K=cols[0,64), V=cols[64,128)
__device__ float g_O [(size_t)MROWS * DIM];   // attention out, [B,N,H*D]

// ---------------------------------------------------------------------------
// Reg-blocked fp32 GEMM: C[M,Ncol] = A[M,Kd] * B[Kd,Ncol] (+bias per col)
// BM=BN=64, BK=16, 256 threads, 4x4 per thread. M%64==0, Ncol%64==0, Kd%16==0.
// ---------------------------------------------------------------------------
__global__ void sgemm64(const float* __restrict__ A, const float* __restrict__ B,
                        const float* __restrict__ bias, float* __restrict__ C,
                        int M, int Kd, int Ncol)
{
    __shared__ float As[16][68];   // [k][row] transposed, padded
    __shared__ float Bs[16][68];   // [k][col], padded

    const int tid    = threadIdx.x;
    const int rowBlk = blockIdx.y * 64;
    const int colBlk = blockIdx.x * 64;
    const int tx = tid & 15;       // 0..15
    const int ty = tid >> 4;       // 0..15

    // A-load: each thread grabs one float4 of a row's K-slice
    const int aRow = tid >> 2;           // 0..63
    const int aK4  = (tid & 3) << 2;     // 0,4,8,12
    // B-load: each thread grabs one float4 of a k-row's col-slice
    const int bRow = tid >> 4;           // 0..15
    const int bC4  = (tid & 15) << 2;    // 0..60

    float acc[4][4] = {};

    for (int k0 = 0; k0 < Kd; k0 += 16) {
        float4 av = *(const float4*)(A + (size_t)(rowBlk + aRow) * Kd + k0 + aK4);
        As[aK4 + 0][aRow] = av.x;
        As[aK4 + 1][aRow] = av.y;
        As[aK4 + 2][aRow] = av.z;
        As[aK4 + 3][aRow] = av.w;
        float4 bv = *(const float4*)(B + (size_t)(k0 + bRow) * Ncol + colBlk + bC4);
        Bs[bRow][bC4 + 0] = bv.x;
        Bs[bRow][bC4 + 1] = bv.y;
        Bs[bRow][bC4 + 2] = bv.z;
        Bs[bRow][bC4 + 3] = bv.w;
        __syncthreads();

        #pragma unroll
        for (int kk = 0; kk < 16; ++kk) {
            float ar[4], br[4];
            #pragma unroll
            for (int i = 0; i < 4; ++i) ar[i] = As[kk][ty * 4 + i];
            #pragma unroll
            for (int j = 0; j < 4; ++j) br[j] = Bs[kk][tx * 4 + j];
            #pragma unroll
            for (int i = 0; i < 4; ++i)
                #pragma unroll
                for (int j = 0; j < 4; ++j)
                    acc[i][j] += ar[i] * br[j];
        }
        __syncthreads();
    }

    #pragma unroll
    for (int i = 0; i < 4; ++i) {
        const int r = rowBlk + ty * 4 + i;
        #pragma unroll
        for (int j = 0; j < 4; ++j) {
            const int c = colBlk + tx * 4 + j;
            float v = acc[i][j];
            if (bias) v += bias[c];
            C[(size_t)r * Ncol + c] = v;
        }
    }
}

// ---------------------------------------------------------------------------
// Attention: one block per (b, h, query-row n). 256 threads, keys-parallel.
// MQA: K/V shared across heads (g_KV row = [K(64) | V(64)]).
// ---------------------------------------------------------------------------
__global__ void attn_row_kernel(const float* __restrict__ Q,
                                const float* __restrict__ KV,
                                float* __restrict__ O)
{
    const int n = blockIdx.x;
    const int h = blockIdx.y;
    const int b = blockIdx.z;
    const int tid = threadIdx.x;

    __shared__ float qs[HDIM];
    __shared__ float logits[SEQ];
    __shared__ float red[256];
    __shared__ float osum[4][HDIM];

    const size_t rowBase = (size_t)(b * SEQ + n) * DIM + h * HDIM;
    if (tid < HDIM) qs[tid] = Q[rowBase + tid];
    __syncthreads();

    const float* Kb = KV + (size_t)b * SEQ * KVW;

    // Phase 1: logits + running max (8 keys per thread)
    float lmax = -1e30f;
    #pragma unroll
    for (int jj = 0; jj < 8; ++jj) {
        const int j = tid + jj * 256;
        const float* krow = Kb + (size_t)j * KVW;
        float dot = 0.f;
        #pragma unroll
        for (int d = 0; d < HDIM; ++d) dot += qs[d] * krow[d];
        dot *= ATT_SCALE;
        logits[j] = dot;
        lmax = fmaxf(lmax, dot);
    }
    red[tid] = lmax;
    __syncthreads();
    #pragma unroll
    for (int s = 128; s > 0; s >>= 1) {
        if (tid < s) red[tid] = fmaxf(red[tid], red[tid + s]);
        __syncthreads();
    }
    const float m = red[0];
    __syncthreads();

    // Phase 2: exp + sum
    float lsum = 0.f;
    #pragma unroll
    for (int jj = 0; jj < 8; ++jj) {
        const int j = tid + jj * 256;
        const float p = expf(logits[j] - m);
        logits[j] = p;
        lsum += p;
    }
    red[tid] = lsum;
    __syncthreads();
    #pragma unroll
    for (int s = 128; s > 0; s >>= 1) {
        if (tid < s) red[tid] += red[tid + s];
        __syncthreads();
    }
    const float inv = 1.f / red[0];
    __syncthreads();

    // Phase 3: out[d] = sum_j p[j] * V[j][d]; thread = (chunk c, dim d), coalesced over d
    const int d = tid & 63;
    const int c = tid >> 6;           // 0..3, 512 keys each
    const float* Vb = Kb + HDIM;
    float acc = 0.f;
    const int j0 = c * 512;
    for (int j = j0; j < j0 + 512; ++j)
        acc += logits[j] * Vb[(size_t)j * KVW + d];
    osum[c][d] = acc;
    __syncthreads();

    if (tid < HDIM) {
        const float o = (osum[0][tid] + osum[1][tid] + osum[2][tid] + osum[3][tid]) * inv;
        O[rowBase + tid] = o;
    }
}

// ---------------------------------------------------------------------------
extern "C" void kernel_launch(void* const* d_in, const int* in_sizes, int n_in,
                              void* d_out, int out_size)
{
    const float* x     = (const float*)d_in[0];  // [B,N,768]
    const float* Wq    = (const float*)d_in[1];  // [768,768]
    const float* Wkv   = (const float*)d_in[2];  // [768,128]
    const float* Wproj = (const float*)d_in[3];  // [768,768]
    const float* bproj = (const float*)d_in[4];  // [768]
    float* out = (float*)d_out;                  // [B,N,768]

    float* Q  = nullptr; cudaGetSymbolAddress((void**)&Q,  g_Q);
    float* KV = nullptr; cudaGetSymbolAddress((void**)&KV, g_KV);
    float* O  = nullptr; cudaGetSymbolAddress((void**)&O,  g_O);

    // 1) Q = x @ Wq
    {
        dim3 grid(DIM / 64, MROWS / 64);
        sgemm64<<<grid, 256>>>(x, Wq, nullptr, Q, MROWS, DIM, DIM);
    }
    // 2) KV = x @ Wkv
    {
        dim3 grid(KVW / 64, MROWS / 64);
        sgemm64<<<grid, 256>>>(x, Wkv, nullptr, KV, MROWS, DIM, KVW);
    }
    // 3) attention
    {
        dim3 grid(SEQ, NHEAD, BATCH);
        attn_row_kernel<<<grid, 256>>>(Q, KV, O);
    }
    // 4) out = O @ Wproj + bproj
    {
        dim3 grid(DIM / 64, MROWS / 64);
        sgemm64<<<grid, 256>>>(O, Wproj, bproj, out, MROWS, DIM, DIM);
    }
}

// round 2
// speedup vs baseline: 20.0223x; 20.0223x over previous
#include <cuda_runtime.h>
#include <cuda_bf16.h>
#include <math.h>

// Problem constants (Attention_146028888650)
#define BATCH 2
#define SEQ   2048
#define DIM   768
#define NHEAD 12
#define HDIM  64
#define KVW   128           // 2*HDIM
#define MROWS (BATCH*SEQ)   // 4096
#define ATT_SCALE 0.125f    // 64^-0.5

// Scratch (device globals — no runtime allocation allowed)
__device__ float g_Q [(size_t)MROWS * DIM];   // x @ Wq   -> [B*N, 768]
__device__ float g_KV[(size_t)MROWS * KVW];   // x @ Wkv  -> [B*N, 128]; K=[0,64), V=[64,128)
__device__ float g_O [(size_t)MROWS * DIM];   // attention out

// ---------------------------------------------------------------------------
// Reg-blocked fp32 GEMM: C[M,Ncol] = A[M,Kd] * B[Kd,Ncol] (+bias per col)
// ---------------------------------------------------------------------------
__global__ void sgemm64(const float* __restrict__ A, const float* __restrict__ B,
                        const float* __restrict__ bias, float* __restrict__ C,
                        int M, int Kd, int Ncol)
{
    __shared__ float As[16][68];
    __shared__ float Bs[16][68];

    const int tid    = threadIdx.x;
    const int rowBlk = blockIdx.y * 64;
    const int colBlk = blockIdx.x * 64;
    const int tx = tid & 15;
    const int ty = tid >> 4;

    const int aRow = tid >> 2;
    const int aK4  = (tid & 3) << 2;
    const int bRow = tid >> 4;
    const int bC4  = (tid & 15) << 2;

    float acc[4][4] = {};

    for (int k0 = 0; k0 < Kd; k0 += 16) {
        float4 av = *(const float4*)(A + (size_t)(rowBlk + aRow) * Kd + k0 + aK4);
        As[aK4 + 0][aRow] = av.x;
        As[aK4 + 1][aRow] = av.y;
        As[aK4 + 2][aRow] = av.z;
        As[aK4 + 3][aRow] = av.w;
        float4 bv = *(const float4*)(B + (size_t)(k0 + bRow) * Ncol + colBlk + bC4);
        Bs[bRow][bC4 + 0] = bv.x;
        Bs[bRow][bC4 + 1] = bv.y;
        Bs[bRow][bC4 + 2] = bv.z;
        Bs[bRow][bC4 + 3] = bv.w;
        __syncthreads();

        #pragma unroll
        for (int kk = 0; kk < 16; ++kk) {
            float ar[4], br[4];
            #pragma unroll
            for (int i = 0; i < 4; ++i) ar[i] = As[kk][ty * 4 + i];
            #pragma unroll
            for (int j = 0; j < 4; ++j) br[j] = Bs[kk][tx * 4 + j];
            #pragma unroll
            for (int i = 0; i < 4; ++i)
                #pragma unroll
                for (int j = 0; j < 4; ++j)
                    acc[i][j] += ar[i] * br[j];
        }
        __syncthreads();
    }

    #pragma unroll
    for (int i = 0; i < 4; ++i) {
        const int r = rowBlk + ty * 4 + i;
        #pragma unroll
        for (int j = 0; j < 4; ++j) {
            const int c = colBlk + tx * 4 + j;
            float v = acc[i][j];
            if (bias) v += bias[c];
            C[(size_t)r * Ncol + c] = v;
        }
    }
}

// ---------------------------------------------------------------------------
// Flash-attention tile kernel: 64 queries x 64-key tiles, fp32, online softmax.
// grid = (SEQ/64, NHEAD, BATCH), 256 threads (16x16, 4x4 frags).
// Dynamic smem layout (floats):
//   Qs [64*64]   @ 0      (stride 64)  -- pre-scaled by ATT_SCALE
//   Ks [64*65]   @ 4096   (stride 65)  -- reused as P tile after S compute
//   Vs [64*64]   @ 8256   (stride 64)
// total = 12352 floats = 49408 bytes
// ---------------------------------------------------------------------------
#define SM_Q 0
#define SM_K 4096
#define SM_V 8256
#define SMEM_FLOATS 12352

__global__ void attn_flash_kernel(const float* __restrict__ Q,
                                  const float* __restrict__ KV,
                                  float* __restrict__ O)
{
    extern __shared__ float sm[];
    float* Qs = sm + SM_Q;
    float* Ks = sm + SM_K;   // also P tile
    float* Vs = sm + SM_V;

    const int tid = threadIdx.x;
    const int tx  = tid & 15;
    const int ty  = tid >> 4;
    const int qBase = blockIdx.x * 64;
    const int h     = blockIdx.y;
    const int b     = blockIdx.z;

    // Load Q tile (64 rows x 64 dims), pre-scaled
    #pragma unroll
    for (int r = 0; r < 4; ++r) {
        const int idx = tid + r * 256;          // 0..1023 float4s
        const int row = idx >> 4;
        const int c4  = (idx & 15) << 2;
        float4 v = *(const float4*)(Q + (size_t)(b * SEQ + qBase + row) * DIM + h * HDIM + c4);
        Qs[row * 64 + c4 + 0] = v.x * ATT_SCALE;
        Qs[row * 64 + c4 + 1] = v.y * ATT_SCALE;
        Qs[row * 64 + c4 + 2] = v.z * ATT_SCALE;
        Qs[row * 64 + c4 + 3] = v.w * ATT_SCALE;
    }

    float acc[4][4] = {};
    float m[4] = {-1e30f, -1e30f, -1e30f, -1e30f};
    float l[4] = {};

    const float* KVb = KV + (size_t)b * SEQ * KVW;

    for (int kb = 0; kb < SEQ; kb += 64) {
        __syncthreads();   // previous iter done with Ks(P)/Vs; Q ready on iter 0
        // Load K and V tiles (64 keys x 64 dims each)
        #pragma unroll
        for (int r = 0; r < 4; ++r) {
            const int idx = tid + r * 256;
            const int j   = idx >> 4;
            const int c4  = (idx & 15) << 2;
            const float* src = KVb + (size_t)(kb + j) * KVW;
            float4 kv4 = *(const float4*)(src + c4);
            Ks[j * 65 + c4 + 0] = kv4.x;
            Ks[j * 65 + c4 + 1] = kv4.y;
            Ks[j * 65 + c4 + 2] = kv4.z;
            Ks[j * 65 + c4 + 3] = kv4.w;
            float4 vv4 = *(const float4*)(src + HDIM + c4);
            Vs[j * 64 + c4 + 0] = vv4.x;
            Vs[j * 64 + c4 + 1] = vv4.y;
            Vs[j * 64 + c4 + 2] = vv4.z;
            Vs[j * 64 + c4 + 3] = vv4.w;
        }
        __syncthreads();

        // S = Q * K^T  (4x4 fragment per thread)
        float s[4][4] = {};
        #pragma unroll
        for (int d = 0; d < 64; ++d) {
            float ar[4], br[4];
            #pragma unroll
            for (int i = 0; i < 4; ++i) ar[i] = Qs[(ty * 4 + i) * 64 + d];
            #pragma unroll
            for (int j = 0; j < 4; ++j) br[j] = Ks[(tx * 4 + j) * 65 + d];
            #pragma unroll
            for (int i = 0; i < 4; ++i)
                #pragma unroll
                for (int j = 0; j < 4; ++j)
                    s[i][j] += ar[i] * br[j];
        }
        __syncthreads();   // all threads done reading Ks before it becomes P

        // Online softmax (row groups = 16 lanes sharing ty)
        #pragma unroll
        for (int i = 0; i < 4; ++i) {
            float tmax = fmaxf(fmaxf(s[i][0], s[i][1]), fmaxf(s[i][2], s[i][3]));
            #pragma unroll
            for (int off = 1; off < 16; off <<= 1)
                tmax = fmaxf(tmax, __shfl_xor_sync(0xffffffffu, tmax, off, 16));
            const float nm   = fmaxf(m[i], tmax);
            const float corr = __expf(m[i] - nm);
            m[i] = nm;
            float psum = 0.f;
            #pragma unroll
            for (int j = 0; j < 4; ++j) {
                const float p = __expf(s[i][j] - nm);
                s[i][j] = p;
                psum += p;
            }
            #pragma unroll
            for (int off = 1; off < 16; off <<= 1)
                psum += __shfl_xor_sync(0xffffffffu, psum, off, 16);
            l[i] = l[i] * corr + psum;
            #pragma unroll
            for (int j = 0; j < 4; ++j) acc[i][j] *= corr;
        }

        // Write P tile into Ks buffer
        #pragma unroll
        for (int i = 0; i < 4; ++i)
            #pragma unroll
            for (int j = 0; j < 4; ++j)
                Ks[(ty * 4 + i) * 65 + tx * 4 + j] = s[i][j];
        __syncthreads();

        // O += P * V
        #pragma unroll
        for (int k = 0; k < 64; ++k) {
            float pr[4], vr[4];
            #pragma unroll
            for (int i = 0; i < 4; ++i) pr[i] = Ks[(ty * 4 + i) * 65 + k];
            #pragma unroll
            for (int j = 0; j < 4; ++j) vr[j] = Vs[k * 64 + tx * 4 + j];
            #pragma unroll
            for (int i = 0; i < 4; ++i)
                #pragma unroll
                for (int j = 0; j < 4; ++j)
                    acc[i][j] += pr[i] * vr[j];
        }
    }

    // Normalize and store
    #pragma unroll
    for (int i = 0; i < 4; ++i) {
        const float inv = 1.f / l[i];
        const size_t row = (size_t)(b * SEQ + qBase + ty * 4 + i) * DIM + h * HDIM;
        #pragma unroll
        for (int j = 0; j < 4; ++j)
            O[row + tx * 4 + j] = acc[i][j] * inv;
    }
}

// ---------------------------------------------------------------------------
extern "C" void kernel_launch(void* const* d_in, const int* in_sizes, int n_in,
                              void* d_out, int out_size)
{
    const float* x     = (const float*)d_in[0];
    const float* Wq    = (const float*)d_in[1];
    const float* Wkv   = (const float*)d_in[2];
    const float* Wproj = (const float*)d_in[3];
    const float* bproj = (const float*)d_in[4];
    float* out = (float*)d_out;

    float* Q  = nullptr; cudaGetSymbolAddress((void**)&Q,  g_Q);
    float* KV = nullptr; cudaGetSymbolAddress((void**)&KV, g_KV);
    float* O  = nullptr; cudaGetSymbolAddress((void**)&O,  g_O);

    static bool attr_set = false;
    if (!attr_set) {
        cudaFuncSetAttribute(attn_flash_kernel,
                             cudaFuncAttributeMaxDynamicSharedMemorySize,
                             SMEM_FLOATS * (int)sizeof(float));
        attr_set = true;
    }

    // 1) Q = x @ Wq
    {
        dim3 grid(DIM / 64, MROWS / 64);
        sgemm64<<<grid, 256>>>(x, Wq, nullptr, Q, MROWS, DIM, DIM);
    }
    // 2) KV = x @ Wkv
    {
        dim3 grid(KVW / 64, MROWS / 64);
        sgemm64<<<grid, 256>>>(x, Wkv, nullptr, KV, MROWS, DIM, KVW);
    }
    // 3) flash attention
    {
        dim3 grid(SEQ / 64, NHEAD, BATCH);
        attn_flash_kernel<<<grid, 256, SMEM_FLOATS * sizeof(float)>>>(Q, KV, O);
    }
    // 4) out = O @ Wproj + bproj
    {
        dim3 grid(DIM / 64, MROWS / 64);
        sgemm64<<<grid, 256>>>(O, Wproj, bproj, out, MROWS, DIM, DIM);
    }
}

// round 4
// speedup vs baseline: 34.6597x; 1.7311x over previous
#include <cuda_runtime.h>
#include <cuda_bf16.h>
#include <math.h>
#include <stdint.h>

// Problem constants (Attention_146028888650)
#define BATCH 2
#define SEQ   2048
#define DIM   768
#define NHEAD 12
#define HDIM  64
#define KVW   128
#define MROWS (BATCH*SEQ)   // 4096
#define ATT_SCALE 0.125f

// Scratch (device globals — no runtime allocation allowed)
__device__ float g_Q [(size_t)MROWS * DIM];
__device__ float g_KV[(size_t)MROWS * KVW];
__device__ float g_O [(size_t)MROWS * DIM];
// Split-bf16 operands for tensor-core attention
__device__ __nv_bfloat16 g_Qh[(size_t)MROWS * DIM];
__device__ __nv_bfloat16 g_Ql[(size_t)MROWS * DIM];
__device__ __nv_bfloat16 g_Kh[(size_t)BATCH * SEQ * HDIM];
__device__ __nv_bfloat16 g_Kl[(size_t)BATCH * SEQ * HDIM];
__device__ __nv_bfloat16 g_Vh[(size_t)BATCH * SEQ * HDIM];
__device__ __nv_bfloat16 g_Vl[(size_t)BATCH * SEQ * HDIM];

// ---------------------------------------------------------------------------
// Reg-blocked fp32 GEMM: C = A*B (+bias)
// ---------------------------------------------------------------------------
__global__ void sgemm64(const float* __restrict__ A, const float* __restrict__ B,
                        const float* __restrict__ bias, float* __restrict__ C,
                        int M, int Kd, int Ncol)
{
    __shared__ float As[16][68];
    __shared__ float Bs[16][68];

    const int tid    = threadIdx.x;
    const int rowBlk = blockIdx.y * 64;
    const int colBlk = blockIdx.x * 64;
    const int tx = tid & 15;
    const int ty = tid >> 4;

    const int aRow = tid >> 2;
    const int aK4  = (tid & 3) << 2;
    const int bRow = tid >> 4;
    const int bC4  = (tid & 15) << 2;

    float acc[4][4] = {};

    for (int k0 = 0; k0 < Kd; k0 += 16) {
        float4 av = *(const float4*)(A + (size_t)(rowBlk + aRow) * Kd + k0 + aK4);
        As[aK4 + 0][aRow] = av.x;
        As[aK4 + 1][aRow] = av.y;
        As[aK4 + 2][aRow] = av.z;
        As[aK4 + 3][aRow] = av.w;
        float4 bv = *(const float4*)(B + (size_t)(k0 + bRow) * Ncol + colBlk + bC4);
        Bs[bRow][bC4 + 0] = bv.x;
        Bs[bRow][bC4 + 1] = bv.y;
        Bs[bRow][bC4 + 2] = bv.z;
        Bs[bRow][bC4 + 3] = bv.w;
        __syncthreads();

        #pragma unroll
        for (int kk = 0; kk < 16; ++kk) {
            float ar[4], br[4];
            #pragma unroll
            for (int i = 0; i < 4; ++i) ar[i] = As[kk][ty * 4 + i];
            #pragma unroll
            for (int j = 0; j < 4; ++j) br[j] = Bs[kk][tx * 4 + j];
            #pragma unroll
            for (int i = 0; i < 4; ++i)
                #pragma unroll
                for (int j = 0; j < 4; ++j)
                    acc[i][j] += ar[i] * br[j];
        }
        __syncthreads();
    }

    #pragma unroll
    for (int i = 0; i < 4; ++i) {
        const int r = rowBlk + ty * 4 + i;
        #pragma unroll
        for (int j = 0; j < 4; ++j) {
            const int c = colBlk + tx * 4 + j;
            float v = acc[i][j];
            if (bias) v += bias[c];
            C[(size_t)r * Ncol + c] = v;
        }
    }
}

// ---------------------------------------------------------------------------
// Conversion kernels: fp32 -> split bf16 (hi + lo)
// ---------------------------------------------------------------------------
__device__ __forceinline__ uint32_t pack2(float x, float y) {
    __nv_bfloat162 t = __float22bfloat162_rn(make_float2(x, y));
    return *reinterpret_cast<uint32_t*>(&t);
}
__device__ __forceinline__ float2 unpack2(uint32_t u) {
    __nv_bfloat162 t = *reinterpret_cast<__nv_bfloat162*>(&u);
    return __bfloat1622float2(t);
}

// Q: scale by 0.125 (exact power of 2), split
__global__ void cvt_q_kernel(const float* __restrict__ Q,
                             __nv_bfloat16* __restrict__ Qh,
                             __nv_bfloat16* __restrict__ Ql)
{
    const int i = blockIdx.x * blockDim.x + threadIdx.x;  // float4 index
    float4 v = ((const float4*)Q)[i];
    v.x *= ATT_SCALE; v.y *= ATT_SCALE; v.z *= ATT_SCALE; v.w *= ATT_SCALE;
    uint32_t h0 = pack2(v.x, v.y), h1 = pack2(v.z, v.w);
    float2 f0 = unpack2(h0), f1 = unpack2(h1);
    uint32_t l0 = pack2(v.x - f0.x, v.y - f0.y), l1 = pack2(v.z - f1.x, v.w - f1.y);
    ((uint2*)Qh)[i] = make_uint2(h0, h1);
    ((uint2*)Ql)[i] = make_uint2(l0, l1);
}

// KV: row r of g_KV = [K(64) | V(64)] -> Kh/Kl/Vh/Vl at row r
__global__ void cvt_kv_kernel(const float* __restrict__ KV,
                              __nv_bfloat16* __restrict__ Kh, __nv_bfloat16* __restrict__ Kl,
                              __nv_bfloat16* __restrict__ Vh, __nv_bfloat16* __restrict__ Vl)
{
    const int i = blockIdx.x * blockDim.x + threadIdx.x;  // float4 index, 32 per row
    const int r  = i >> 5;
    const int c4 = i & 31;
    float4 v = ((const float4*)KV)[i];
    uint32_t h0 = pack2(v.x, v.y), h1 = pack2(v.z, v.w);
    float2 f0 = unpack2(h0), f1 = unpack2(h1);
    uint32_t l0 = pack2(v.x - f0.x, v.y - f0.y), l1 = pack2(v.z - f1.x, v.w - f1.y);
    if (c4 < 16) {
        const int di = r * 16 + c4;
        ((uint2*)Kh)[di] = make_uint2(h0, h1);
        ((uint2*)Kl)[di] = make_uint2(l0, l1);
    } else {
        const int di = r * 16 + (c4 - 16);
        ((uint2*)Vh)[di] = make_uint2(h0, h1);
        ((uint2*)Vl)[di] = make_uint2(l0, l1);
    }
}

// ---------------------------------------------------------------------------
// Tensor-core flash attention: 64q x 64k tiles, 4 warps, split-bf16 mma.sync.
// ---------------------------------------------------------------------------
#define LSTR 72   // smem row stride in bf16 elements (144 B, conflict-free)

__device__ __forceinline__ uint32_t smem_addr(const void* p) {
    return (uint32_t)__cvta_generic_to_shared(p);
}

#define MMA_BF16(c, a, b)                                                        \
    asm volatile("mma.sync.aligned.m16n8k16.row.col.f32.bf16.bf16.f32 "          \
                 "{%0,%1,%2,%3},{%4,%5,%6,%7},{%8,%9},{%0,%1,%2,%3};"            \
                 : "+f"((c)[0]), "+f"((c)[1]), "+f"((c)[2]), "+f"((c)[3])        \
                 : "r"((a)[0]), "r"((a)[1]), "r"((a)[2]), "r"((a)[3]),           \
                   "r"((b)[0]), "r"((b)[1]))

#define LDSM_X4(r, addr)                                                         \
    asm volatile("ldmatrix.sync.aligned.m8n8.x4.shared.b16 {%0,%1,%2,%3}, [%4];" \
                 : "=r"((r)[0]), "=r"((r)[1]), "=r"((r)[2]), "=r"((r)[3])        \
                 : "r"(addr))
#define LDSM_X2(r, addr)                                                         \
    asm volatile("ldmatrix.sync.aligned.m8n8.x2.shared.b16 {%0,%1}, [%2];"       \
                 : "=r"((r)[0]), "=r"((r)[1]) : "r"(addr))
#define LDSM_X2T(r, addr)                                                        \
    asm volatile("ldmatrix.sync.aligned.m8n8.x2.trans.shared.b16 {%0,%1}, [%2];" \
                 : "=r"((r)[0]), "=r"((r)[1]) : "r"(addr))

__global__ __launch_bounds__(128)
void attn_mma_kernel(const __nv_bfloat16* __restrict__ Qh, const __nv_bfloat16* __restrict__ Ql,
                     const __nv_bfloat16* __restrict__ Kh, const __nv_bfloat16* __restrict__ Kl,
                     const __nv_bfloat16* __restrict__ Vh, const __nv_bfloat16* __restrict__ Vl,
                     float* __restrict__ O)
{
    extern __shared__ __nv_bfloat16 sm[];
    __nv_bfloat16* sQh = sm;
    __nv_bfloat16* sQl = sm + 4608;
    __nv_bfloat16* sKh = sm + 9216;
    __nv_bfloat16* sKl = sm + 13824;
    __nv_bfloat16* sVh = sm + 18432;
    __nv_bfloat16* sVl = sm + 23040;

    const int tid  = threadIdx.x;
    const int lane = tid & 31;
    const int w    = tid >> 5;       // warp 0..3: rows w*16..w*16+15
    const int qBase = blockIdx.x * 64;
    const int h     = blockIdx.y;
    const int b     = blockIdx.z;

    // Load Q tile (64 x 64) for this head, hi+lo
    {
        const __nv_bfloat16* gqh = Qh + (size_t)(b * SEQ + qBase) * DIM + h * HDIM;
        const __nv_bfloat16* gql = Ql + (size_t)(b * SEQ + qBase) * DIM + h * HDIM;
        #pragma unroll
        for (int i = 0; i < 4; ++i) {
            const int idx = tid + i * 128;      // 512 uint4 per array
            const int row = idx >> 3;
            const int c   = (idx & 7) * 8;      // bf16 col
            *(uint4*)(sQh + row * LSTR + c) = *(const uint4*)(gqh + (size_t)row * DIM + c);
            *(uint4*)(sQl + row * LSTR + c) = *(const uint4*)(gql + (size_t)row * DIM + c);
        }
    }

    float oc[8][4] = {};
    float m0 = -1e30f, m1 = -1e30f, l0 = 0.f, l1 = 0.f;

    const __nv_bfloat16* gkh = Kh + (size_t)b * SEQ * HDIM;
    const __nv_bfloat16* gkl = Kl + (size_t)b * SEQ * HDIM;
    const __nv_bfloat16* gvh = Vh + (size_t)b * SEQ * HDIM;
    const __nv_bfloat16* gvl = Vl + (size_t)b * SEQ * HDIM;

    // ldmatrix lane addressing helpers
    const int l16 = lane & 15;
    const int aRow = w * 16 + l16;
    const int aColBase = (lane >> 4) * 8;
    const int bRowOff = l16 & 7;
    const int bColOff = (l16 >> 3) * 8;

    for (int kt = 0; kt < SEQ; kt += 64) {
        __syncthreads();   // prior iter done with K/V smem
        // Load K/V tiles (4 arrays x 64x64)
        #pragma unroll
        for (int i = 0; i < 4; ++i) {
            const int idx = tid + i * 128;
            const int row = idx >> 3;
            const int c   = (idx & 7) * 8;
            const size_t g = (size_t)(kt + row) * HDIM + c;
            *(uint4*)(sKh + row * LSTR + c) = *(const uint4*)(gkh + g);
            *(uint4*)(sKl + row * LSTR + c) = *(const uint4*)(gkl + g);
            *(uint4*)(sVh + row * LSTR + c) = *(const uint4*)(gvh + g);
            *(uint4*)(sVl + row * LSTR + c) = *(const uint4*)(gvl + g);
        }
        __syncthreads();

        // ---- S = Q K^T (split bf16: hh + hl + lh) ----
        float sc[8][4] = {};
        #pragma unroll
        for (int ks = 0; ks < 4; ++ks) {
            uint32_t aqh[4], aql[4];
            const uint32_t qa = smem_addr(sQh + aRow * LSTR + ks * 16 + aColBase);
            const uint32_t qb = smem_addr(sQl + aRow * LSTR + ks * 16 + aColBase);
            LDSM_X4(aqh, qa);
            LDSM_X4(aql, qb);
            #pragma unroll
            for (int nt = 0; nt < 8; ++nt) {
                uint32_t bkh[2], bkl[2];
                const int boff = (nt * 8 + bRowOff) * LSTR + ks * 16 + bColOff;
                LDSM_X2(bkh, smem_addr(sKh + boff));
                LDSM_X2(bkl, smem_addr(sKl + boff));
                MMA_BF16(sc[nt], aqh, bkh);
                MMA_BF16(sc[nt], aqh, bkl);
                MMA_BF16(sc[nt], aql, bkh);
            }
        }

        // ---- online softmax ----
        float mx0 = -1e30f, mx1 = -1e30f;
        #pragma unroll
        for (int nt = 0; nt < 8; ++nt) {
            mx0 = fmaxf(mx0, fmaxf(sc[nt][0], sc[nt][1]));
            mx1 = fmaxf(mx1, fmaxf(sc[nt][2], sc[nt][3]));
        }
        mx0 = fmaxf(mx0, __shfl_xor_sync(0xffffffffu, mx0, 1));
        mx0 = fmaxf(mx0, __shfl_xor_sync(0xffffffffu, mx0, 2));
        mx1 = fmaxf(mx1, __shfl_xor_sync(0xffffffffu, mx1, 1));
        mx1 = fmaxf(mx1, __shfl_xor_sync(0xffffffffu, mx1, 2));
        const float mn0 = fmaxf(m0, mx0);
        const float mn1 = fmaxf(m1, mx1);
        const float cr0 = __expf(m0 - mn0);
        const float cr1 = __expf(m1 - mn1);
        m0 = mn0; m1 = mn1;

        float s0 = 0.f, s1 = 0.f;
        #pragma unroll
        for (int nt = 0; nt < 8; ++nt) {
            sc[nt][0] = __expf(sc[nt][0] - mn0);
            sc[nt][1] = __expf(sc[nt][1] - mn0);
            sc[nt][2] = __expf(sc[nt][2] - mn1);
            sc[nt][3] = __expf(sc[nt][3] - mn1);
            s0 += sc[nt][0] + sc[nt][1];
            s1 += sc[nt][2] + sc[nt][3];
        }
        s0 += __shfl_xor_sync(0xffffffffu, s0, 1);
        s0 += __shfl_xor_sync(0xffffffffu, s0, 2);
        s1 += __shfl_xor_sync(0xffffffffu, s1, 1);
        s1 += __shfl_xor_sync(0xffffffffu, s1, 2);
        l0 = l0 * cr0 + s0;
        l1 = l1 * cr1 + s1;
        #pragma unroll
        for (int dt = 0; dt < 8; ++dt) {
            oc[dt][0] *= cr0; oc[dt][1] *= cr0;
            oc[dt][2] *= cr1; oc[dt][3] *= cr1;
        }

        // ---- O += P V (split bf16) ----
        #pragma unroll
        for (int g = 0; g < 4; ++g) {
            const int t0 = 2 * g, t1 = 2 * g + 1;
            uint32_t ah[4], al[4];
            ah[0] = pack2(sc[t0][0], sc[t0][1]);
            ah[1] = pack2(sc[t0][2], sc[t0][3]);
            ah[2] = pack2(sc[t1][0], sc[t1][1]);
            ah[3] = pack2(sc[t1][2], sc[t1][3]);
            {
                float2 f;
                f = unpack2(ah[0]); al[0] = pack2(sc[t0][0] - f.x, sc[t0][1] - f.y);
                f = unpack2(ah[1]); al[1] = pack2(sc[t0][2] - f.x, sc[t0][3] - f.y);
                f = unpack2(ah[2]); al[2] = pack2(sc[t1][0] - f.x, sc[t1][1] - f.y);
                f = unpack2(ah[3]); al[3] = pack2(sc[t1][2] - f.x, sc[t1][3] - f.y);
            }
            #pragma unroll
            for (int dt = 0; dt < 8; ++dt) {
                uint32_t bvh[2], bvl[2];
                const int voff = (g * 16 + l16) * LSTR + dt * 8;
                LDSM_X2T(bvh, smem_addr(sVh + voff));
                LDSM_X2T(bvl, smem_addr(sVl + voff));
                MMA_BF16(oc[dt], ah, bvh);
                MMA_BF16(oc[dt], ah, bvl);
                MMA_BF16(oc[dt], al, bvh);
            }
        }
    }

    // ---- normalize + store ----
    const float inv0 = 1.f / l0;
    const float inv1 = 1.f / l1;
    const int r0 = w * 16 + (lane >> 2);
    const int r1 = r0 + 8;
    float* orow0 = O + (size_t)(b * SEQ + qBase + r0) * DIM + h * HDIM;
    float* orow1 = O + (size_t)(b * SEQ + qBase + r1) * DIM + h * HDIM;
    #pragma unroll
    for (int dt = 0; dt < 8; ++dt) {
        const int col = dt * 8 + (lane & 3) * 2;
        *(float2*)(orow0 + col) = make_float2(oc[dt][0] * inv0, oc[dt][1] * inv0);
        *(float2*)(orow1 + col) = make_float2(oc[dt][2] * inv1, oc[dt][3] * inv1);
    }
}

#define ATTN_SMEM_BYTES (27648 * 2)   // 6 arrays * 64*72 bf16

// ---------------------------------------------------------------------------
extern "C" void kernel_launch(void* const* d_in, const int* in_sizes, int n_in,
                              void* d_out, int out_size)
{
    const float* x     = (const float*)d_in[0];
    const float* Wq    = (const float*)d_in[1];
    const float* Wkv   = (const float*)d_in[2];
    const float* Wproj = (const float*)d_in[3];
    const float* bproj = (const float*)d_in[4];
    float* out = (float*)d_out;

    float* Q  = nullptr; cudaGetSymbolAddress((void**)&Q,  g_Q);
    float* KV = nullptr; cudaGetSymbolAddress((void**)&KV, g_KV);
    float* O  = nullptr; cudaGetSymbolAddress((void**)&O,  g_O);
    __nv_bfloat16 *Qh, *Ql, *Kh, *Kl, *Vh, *Vl;
    cudaGetSymbolAddress((void**)&Qh, g_Qh);
    cudaGetSymbolAddress((void**)&Ql, g_Ql);
    cudaGetSymbolAddress((void**)&Kh, g_Kh);
    cudaGetSymbolAddress((void**)&Kl, g_Kl);
    cudaGetSymbolAddress((void**)&Vh, g_Vh);
    cudaGetSymbolAddress((void**)&Vl, g_Vl);

    static bool attr_set = false;
    if (!attr_set) {
        cudaFuncSetAttribute(attn_mma_kernel,
                             cudaFuncAttributeMaxDynamicSharedMemorySize,
                             ATTN_SMEM_BYTES);
        attr_set = true;
    }

    // 1) Q = x @ Wq ; KV = x @ Wkv
    {
        dim3 grid(DIM / 64, MROWS / 64);
        sgemm64<<<grid, 256>>>(x, Wq, nullptr, Q, MROWS, DIM, DIM);
    }
    {
        dim3 grid(KVW / 64, MROWS / 64);
        sgemm64<<<grid, 256>>>(x, Wkv, nullptr, KV, MROWS, DIM, KVW);
    }
    // 2) split-bf16 conversions
    cvt_q_kernel <<<(MROWS * DIM / 4) / 256, 256>>>(Q, Qh, Ql);
    cvt_kv_kernel<<<(MROWS * KVW / 4) / 256, 256>>>(KV, Kh, Kl, Vh, Vl);
    // 3) tensor-core flash attention
    {
        dim3 grid(SEQ / 64, NHEAD, BATCH);
        attn_mma_kernel<<<grid, 128, ATTN_SMEM_BYTES>>>(Qh, Ql, Kh, Kl, Vh, Vl, O);
    }
    // 4) out = O @ Wproj + bproj
    {
        dim3 grid(DIM / 64, MROWS / 64);
        sgemm64<<<grid, 256>>>(O, Wproj, bproj, out, MROWS, DIM, DIM);
    }
}

// round 7
// speedup vs baseline: 49.9750x; 1.4419x over previous
#include <cuda_runtime.h>
#include <cuda_bf16.h>
#include <math.h>
#include <stdint.h>

// Problem constants (Attention_146028888650)
#define BATCH 2
#define SEQ   2048
#define DIM   768
#define NHEAD 12
#define HDIM  64
#define KVW   128
#define MROWS (BATCH*SEQ)   // 4096
#define ATT_SCALE 0.125f

typedef __nv_bfloat16 bf16;

// ---------------- scratch (device globals, no runtime alloc) ----------------
__device__ bf16 g_xh [(size_t)MROWS * DIM];
__device__ bf16 g_xl [(size_t)MROWS * DIM];
__device__ bf16 g_Wqh[(size_t)DIM * DIM];
__device__ bf16 g_Wql[(size_t)DIM * DIM];
__device__ bf16 g_Wkh[(size_t)DIM * KVW];
__device__ bf16 g_Wkl[(size_t)DIM * KVW];
__device__ bf16 g_Wph[(size_t)DIM * DIM];
__device__ bf16 g_Wpl[(size_t)DIM * DIM];
__device__ bf16 g_Qh [(size_t)MROWS * DIM];
__device__ bf16 g_Ql [(size_t)MROWS * DIM];
__device__ bf16 g_KVh[(size_t)MROWS * KVW];
__device__ bf16 g_KVl[(size_t)MROWS * KVW];
__device__ bf16 g_Oh [(size_t)MROWS * DIM];
__device__ bf16 g_Ol [(size_t)MROWS * DIM];

// ---------------- helpers ----------------
__device__ __forceinline__ uint32_t pack2(float x, float y) {
    __nv_bfloat162 t = __float22bfloat162_rn(make_float2(x, y));
    return *reinterpret_cast<uint32_t*>(&t);
}
__device__ __forceinline__ float2 unpack2(uint32_t u) {
    __nv_bfloat162 t = *reinterpret_cast<__nv_bfloat162*>(&u);
    return __bfloat1622float2(t);
}
__device__ __forceinline__ uint32_t smem_addr(const void* p) {
    return (uint32_t)__cvta_generic_to_shared(p);
}

#define MMA_BF16(c, a, b)                                                        \
    asm volatile("mma.sync.aligned.m16n8k16.row.col.f32.bf16.bf16.f32 "          \
                 "{%0,%1,%2,%3},{%4,%5,%6,%7},{%8,%9},{%0,%1,%2,%3};"            \
                 : "+f"((c)[0]), "+f"((c)[1]), "+f"((c)[2]), "+f"((c)[3])        \
                 : "r"((a)[0]), "r"((a)[1]), "r"((a)[2]), "r"((a)[3]),           \
                   "r"((b)[0]), "r"((b)[1]))

#define LDSM_X4(r, addr)                                                         \
    asm volatile("ldmatrix.sync.aligned.m8n8.x4.shared.b16 {%0,%1,%2,%3}, [%4];" \
                 : "=r"((r)[0]), "=r"((r)[1]), "=r"((r)[2]), "=r"((r)[3])        \
                 : "r"(addr))
#define LDSM_X2(r, addr)                                                         \
    asm volatile("ldmatrix.sync.aligned.m8n8.x2.shared.b16 {%0,%1}, [%2];"       \
                 : "=r"((r)[0]), "=r"((r)[1]) : "r"(addr))
#define LDSM_X2T(r, addr)                                                        \
    asm volatile("ldmatrix.sync.aligned.m8n8.x2.trans.shared.b16 {%0,%1}, [%2];" \
                 : "=r"((r)[0]), "=r"((r)[1]) : "r"(addr))

// ---------------------------------------------------------------------------
// fp32 -> split bf16 (hi + lo), vectorized float4 in / uint2 out
// ---------------------------------------------------------------------------
__global__ void cvt_split(const float* __restrict__ src,
                          bf16* __restrict__ h, bf16* __restrict__ l)
{
    const int i = blockIdx.x * blockDim.x + threadIdx.x;
    float4 v = ((const float4*)src)[i];
    uint32_t h0 = pack2(v.x, v.y), h1 = pack2(v.z, v.w);
    float2 f0 = unpack2(h0), f1 = unpack2(h1);
    uint32_t l0 = pack2(v.x - f0.x, v.y - f0.y), l1 = pack2(v.z - f1.x, v.w - f1.y);
    ((uint2*)h)[i] = make_uint2(h0, h1);
    ((uint2*)l)[i] = make_uint2(l0, l1);
}

// ---------------------------------------------------------------------------
// Split-bf16 tensor-core GEMM: C[M,N] = A[M,K] * B[K,N]
// A,B given as hi/lo bf16 pairs; fp32 accumulate via 3 MMAs (hh+hl+lh).
// Block tile 128x128, BK=32, 256 threads (8 warps, 2x4, 64x32 warp tiles).
// Epilogue: fp32 (+bias) if Cf != null, else split-bf16 out (scaled).
// ---------------------------------------------------------------------------
#define ASTR 40    // 32 + 8 pad
#define BSTR 136   // 128 + 8 pad

__global__ __launch_bounds__(256)
void gemm_bf16(const bf16* __restrict__ Ah, const bf16* __restrict__ Al,
               const bf16* __restrict__ Bh, const bf16* __restrict__ Bl,
               int M, int K, int N,
               float* __restrict__ Cf, const float* __restrict__ bias,
               bf16* __restrict__ Ch, bf16* __restrict__ Cl, float scale)
{
    __shared__ bf16 sAh[128 * ASTR];
    __shared__ bf16 sAl[128 * ASTR];
    __shared__ bf16 sBh[32 * BSTR];
    __shared__ bf16 sBl[32 * BSTR];

    const int tid  = threadIdx.x;
    const int lane = tid & 31;
    const int l16  = lane & 15;
    const int hi8  = (lane >> 4) * 8;
    const int w    = tid >> 5;
    const int wm   = w >> 2;        // 0..1
    const int wn   = w & 3;         // 0..3
    const int rowBlk = blockIdx.y * 128;
    const int colBlk = blockIdx.x * 128;

    // loader indices
    const int aRow = tid >> 2;            // 0..63 (+64)
    const int aCol = (tid & 3) * 8;       // 0..24
    const int bRow = tid >> 4;            // 0..15 (+16)
    const int bCol = (tid & 15) * 8;      // 0..120

    // ---- load k-tile 0 ----
    #pragma unroll
    for (int i = 0; i < 2; ++i) {
        const int ar = aRow + i * 64;
        *(uint4*)(sAh + ar * ASTR + aCol) = *(const uint4*)(Ah + (size_t)(rowBlk + ar) * K + aCol);
        *(uint4*)(sAl + ar * ASTR + aCol) = *(const uint4*)(Al + (size_t)(rowBlk + ar) * K + aCol);
        const int br = bRow + i * 16;
        *(uint4*)(sBh + br * BSTR + bCol) = *(const uint4*)(Bh + (size_t)br * N + colBlk + bCol);
        *(uint4*)(sBl + br * BSTR + bCol) = *(const uint4*)(Bl + (size_t)br * N + colBlk + bCol);
    }
    __syncthreads();

    float acc[4][4][4] = {};
    uint4 pAh[2], pAl[2], pBh[2], pBl[2];

    const int nk = K / 32;
    for (int kt = 0; kt < nk; ++kt) {
        const bool more = (kt + 1 < nk);
        if (more) {
            const int k0 = (kt + 1) * 32;
            #pragma unroll
            for (int i = 0; i < 2; ++i) {
                const int ar = aRow + i * 64;
                pAh[i] = *(const uint4*)(Ah + (size_t)(rowBlk + ar) * K + k0 + aCol);
                pAl[i] = *(const uint4*)(Al + (size_t)(rowBlk + ar) * K + k0 + aCol);
                const int br = bRow + i * 16;
                pBh[i] = *(const uint4*)(Bh + (size_t)(k0 + br) * N + colBlk + bCol);
                pBl[i] = *(const uint4*)(Bl + (size_t)(k0 + br) * N + colBlk + bCol);
            }
        }

        #pragma unroll
        for (int s = 0; s < 2; ++s) {
            uint32_t bh[4][2], bl[4][2];
            #pragma unroll
            for (int nt = 0; nt < 4; ++nt) {
                const int boff = (s * 16 + l16) * BSTR + wn * 32 + nt * 8;
                LDSM_X2T(bh[nt], smem_addr(sBh + boff));
                LDSM_X2T(bl[nt], smem_addr(sBl + boff));
            }
            #pragma unroll
            for (int mt = 0; mt < 4; ++mt) {
                uint32_t ah[4], al[4];
                const int aoff = (wm * 64 + mt * 16 + l16) * ASTR + s * 16 + hi8;
                LDSM_X4(ah, smem_addr(sAh + aoff));
                LDSM_X4(al, smem_addr(sAl + aoff));
                #pragma unroll
                for (int nt = 0; nt < 4; ++nt) {
                    MMA_BF16(acc[mt][nt], ah, bh[nt]);
                    MMA_BF16(acc[mt][nt], ah, bl[nt]);
                    MMA_BF16(acc[mt][nt], al, bh[nt]);
                }
            }
        }

        if (more) {
            __syncthreads();
            #pragma unroll
            for (int i = 0; i < 2; ++i) {
                const int ar = aRow + i * 64;
                *(uint4*)(sAh + ar * ASTR + aCol) = pAh[i];
                *(uint4*)(sAl + ar * ASTR + aCol) = pAl[i];
                const int br = bRow + i * 16;
                *(uint4*)(sBh + br * BSTR + bCol) = pBh[i];
                *(uint4*)(sBl + br * BSTR + bCol) = pBl[i];
            }
            __syncthreads();
        }
    }

    // ---- epilogue ----
    const int rBase = rowBlk + wm * 64 + (lane >> 2);
    const int cBase = colBlk + wn * 32 + (lane & 3) * 2;
    #pragma unroll
    for (int mt = 0; mt < 4; ++mt) {
        const int r0 = rBase + mt * 16;
        const int r1 = r0 + 8;
        #pragma unroll
        for (int nt = 0; nt < 4; ++nt) {
            const int c = cBase + nt * 8;
            float v00 = acc[mt][nt][0], v01 = acc[mt][nt][1];
            float v10 = acc[mt][nt][2], v11 = acc[mt][nt][3];
            if (Cf) {
                const float b0 = bias ? bias[c] : 0.f;
                const float b1 = bias ? bias[c + 1] : 0.f;
                *(float2*)(Cf + (size_t)r0 * N + c) = make_float2(v00 + b0, v01 + b1);
                *(float2*)(Cf + (size_t)r1 * N + c) = make_float2(v10 + b0, v11 + b1);
            } else {
                v00 *= scale; v01 *= scale; v10 *= scale; v11 *= scale;
                uint32_t h0 = pack2(v00, v01);
                float2 f0 = unpack2(h0);
                uint32_t l0 = pack2(v00 - f0.x, v01 - f0.y);
                uint32_t h1 = pack2(v10, v11);
                float2 f1 = unpack2(h1);
                uint32_t l1 = pack2(v10 - f1.x, v11 - f1.y);
                *(uint32_t*)(Ch + (size_t)r0 * N + c) = h0;
                *(uint32_t*)(Cl + (size_t)r0 * N + c) = l0;
                *(uint32_t*)(Ch + (size_t)r1 * N + c) = h1;
                *(uint32_t*)(Cl + (size_t)r1 * N + c) = l1;
            }
        }
    }
}

// ---------------------------------------------------------------------------
// Tensor-core flash attention: 64q x 64k tiles, 4 warps, split-bf16 mma.
// Reads Q (split, stride DIM) and KV (split, stride KVW: K=[0,64) V=[64,128)).
// Writes O as split bf16 (stride DIM).
// ---------------------------------------------------------------------------
#define LSTR 72

__global__ __launch_bounds__(128)
void attn_mma_kernel(const bf16* __restrict__ Qh, const bf16* __restrict__ Ql,
                     const bf16* __restrict__ KVh, const bf16* __restrict__ KVl,
                     bf16* __restrict__ Oh, bf16* __restrict__ Ol)
{
    extern __shared__ bf16 sm[];
    bf16* sQh = sm;
    bf16* sQl = sm + 4608;
    bf16* sKh = sm + 9216;
    bf16* sKl = sm + 13824;
    bf16* sVh = sm + 18432;
    bf16* sVl = sm + 23040;

    const int tid  = threadIdx.x;
    const int lane = tid & 31;
    const int w    = tid >> 5;
    const int qBase = blockIdx.x * 64;
    const int h     = blockIdx.y;
    const int b     = blockIdx.z;

    // Load Q tile (64 x 64), hi+lo
    {
        const bf16* gqh = Qh + (size_t)(b * SEQ + qBase) * DIM + h * HDIM;
        const bf16* gql = Ql + (size_t)(b * SEQ + qBase) * DIM + h * HDIM;
        #pragma unroll
        for (int i = 0; i < 4; ++i) {
            const int idx = tid + i * 128;
            const int row = idx >> 3;
            const int c   = (idx & 7) * 8;
            *(uint4*)(sQh + row * LSTR + c) = *(const uint4*)(gqh + (size_t)row * DIM + c);
            *(uint4*)(sQl + row * LSTR + c) = *(const uint4*)(gql + (size_t)row * DIM + c);
        }
    }

    float oc[8][4] = {};
    float m0 = -1e30f, m1 = -1e30f, l0 = 0.f, l1 = 0.f;

    const bf16* gkvh = KVh + (size_t)b * SEQ * KVW;
    const bf16* gkvl = KVl + (size_t)b * SEQ * KVW;

    const int l16 = lane & 15;
    const int aRow = w * 16 + l16;
    const int aColBase = (lane >> 4) * 8;
    const int bRowOff = l16 & 7;
    const int bColOff = (l16 >> 3) * 8;

    for (int kt = 0; kt < SEQ; kt += 64) {
        __syncthreads();
        #pragma unroll
        for (int i = 0; i < 4; ++i) {
            const int idx = tid + i * 128;
            const int row = idx >> 3;
            const int c   = (idx & 7) * 8;
            const size_t g = (size_t)(kt + row) * KVW + c;
            *(uint4*)(sKh + row * LSTR + c) = *(const uint4*)(gkvh + g);
            *(uint4*)(sKl + row * LSTR + c) = *(const uint4*)(gkvl + g);
            *(uint4*)(sVh + row * LSTR + c) = *(const uint4*)(gkvh + g + HDIM);
            *(uint4*)(sVl + row * LSTR + c) = *(const uint4*)(gkvl + g + HDIM);
        }
        __syncthreads();

        // ---- S = Q K^T (hh + hl + lh) ----
        float sc[8][4] = {};
        #pragma unroll
        for (int ks = 0; ks < 4; ++ks) {
            uint32_t aqh[4], aql[4];
            LDSM_X4(aqh, smem_addr(sQh + aRow * LSTR + ks * 16 + aColBase));
            LDSM_X4(aql, smem_addr(sQl + aRow * LSTR + ks * 16 + aColBase));
            #pragma unroll
            for (int nt = 0; nt < 8; ++nt) {
                uint32_t bkh[2], bkl[2];
                const int boff = (nt * 8 + bRowOff) * LSTR + ks * 16 + bColOff;
                LDSM_X2(bkh, smem_addr(sKh + boff));
                LDSM_X2(bkl, smem_addr(sKl + boff));
                MMA_BF16(sc[nt], aqh, bkh);
                MMA_BF16(sc[nt], aqh, bkl);
                MMA_BF16(sc[nt], aql, bkh);
            }
        }

        // ---- online softmax ----
        float mx0 = -1e30f, mx1 = -1e30f;
        #pragma unroll
        for (int nt = 0; nt < 8; ++nt) {
            mx0 = fmaxf(mx0, fmaxf(sc[nt][0], sc[nt][1]));
            mx1 = fmaxf(mx1, fmaxf(sc[nt][2], sc[nt][3]));
        }
        mx0 = fmaxf(mx0, __shfl_xor_sync(0xffffffffu, mx0, 1));
        mx0 = fmaxf(mx0, __shfl_xor_sync(0xffffffffu, mx0, 2));
        mx1 = fmaxf(mx1, __shfl_xor_sync(0xffffffffu, mx1, 1));
        mx1 = fmaxf(mx1, __shfl_xor_sync(0xffffffffu, mx1, 2));
        const float mn0 = fmaxf(m0, mx0);
        const float mn1 = fmaxf(m1, mx1);
        const float cr0 = __expf(m0 - mn0);
        const float cr1 = __expf(m1 - mn1);
        m0 = mn0; m1 = mn1;

        float s0 = 0.f, s1 = 0.f;
        #pragma unroll
        for (int nt = 0; nt < 8; ++nt) {
            sc[nt][0] = __expf(sc[nt][0] - mn0);
            sc[nt][1] = __expf(sc[nt][1] - mn0);
            sc[nt][2] = __expf(sc[nt][2] - mn1);
            sc[nt][3] = __expf(sc[nt][3] - mn1);
            s0 += sc[nt][0] + sc[nt][1];
            s1 += sc[nt][2] + sc[nt][3];
        }
        s0 += __shfl_xor_sync(0xffffffffu, s0, 1);
        s0 += __shfl_xor_sync(0xffffffffu, s0, 2);
        s1 += __shfl_xor_sync(0xffffffffu, s1, 1);
        s1 += __shfl_xor_sync(0xffffffffu, s1, 2);
        l0 = l0 * cr0 + s0;
        l1 = l1 * cr1 + s1;
        #pragma unroll
        for (int dt = 0; dt < 8; ++dt) {
            oc[dt][0] *= cr0; oc[dt][1] *= cr0;
            oc[dt][2] *= cr1; oc[dt][3] *= cr1;
        }

        // ---- O += P V (split bf16) ----
        #pragma unroll
        for (int g = 0; g < 4; ++g) {
            const int t0 = 2 * g, t1 = 2 * g + 1;
            uint32_t ah[4], al[4];
            ah[0] = pack2(sc[t0][0], sc[t0][1]);
            ah[1] = pack2(sc[t0][2], sc[t0][3]);
            ah[2] = pack2(sc[t1][0], sc[t1][1]);
            ah[3] = pack2(sc[t1][2], sc[t1][3]);
            {
                float2 f;
                f = unpack2(ah[0]); al[0] = pack2(sc[t0][0] - f.x, sc[t0][1] - f.y);
                f = unpack2(ah[1]); al[1] = pack2(sc[t0][2] - f.x, sc[t0][3] - f.y);
                f = unpack2(ah[2]); al[2] = pack2(sc[t1][0] - f.x, sc[t1][1] - f.y);
                f = unpack2(ah[3]); al[3] = pack2(sc[t1][2] - f.x, sc[t1][3] - f.y);
            }
            #pragma unroll
            for (int dt = 0; dt < 8; ++dt) {
                uint32_t bvh[2], bvl[2];
                const int voff = (g * 16 + l16) * LSTR + dt * 8;
                LDSM_X2T(bvh, smem_addr(sVh + voff));
                LDSM_X2T(bvl, smem_addr(sVl + voff));
                MMA_BF16(oc[dt], ah, bvh);
                MMA_BF16(oc[dt], ah, bvl);
                MMA_BF16(oc[dt], al, bvh);
            }
        }
    }

    // ---- normalize + split-bf16 store ----
    const float inv0 = 1.f / l0;
    const float inv1 = 1.f / l1;
    const int r0 = w * 16 + (lane >> 2);
    const int r1 = r0 + 8;
    const size_t base0 = (size_t)(b * SEQ + qBase + r0) * DIM + h * HDIM;
    const size_t base1 = (size_t)(b * SEQ + qBase + r1) * DIM + h * HDIM;
    #pragma unroll
    for (int dt = 0; dt < 8; ++dt) {
        const int col = dt * 8 + (lane & 3) * 2;
        const float v00 = oc[dt][0] * inv0, v01 = oc[dt][1] * inv0;
        const float v10 = oc[dt][2] * inv1, v11 = oc[dt][3] * inv1;
        uint32_t h0 = pack2(v00, v01);
        float2 f0 = unpack2(h0);
        uint32_t l0w = pack2(v00 - f0.x, v01 - f0.y);
        uint32_t h1 = pack2(v10, v11);
        float2 f1 = unpack2(h1);
        uint32_t l1w = pack2(v10 - f1.x, v11 - f1.y);
        *(uint32_t*)(Oh + base0 + col) = h0;
        *(uint32_t*)(Ol + base0 + col) = l0w;
        *(uint32_t*)(Oh + base1 + col) = h1;
        *(uint32_t*)(Ol + base1 + col) = l1w;
    }
}

#define ATTN_SMEM_BYTES (27648 * 2)

// ---------------------------------------------------------------------------
extern "C" void kernel_launch(void* const* d_in, const int* in_sizes, int n_in,
                              void* d_out, int out_size)
{
    const float* x     = (const float*)d_in[0];
    const float* Wq    = (const float*)d_in[1];
    const float* Wkv   = (const float*)d_in[2];
    const float* Wproj = (const float*)d_in[3];
    const float* bproj = (const float*)d_in[4];
    float* out = (float*)d_out;

    bf16 *xh, *xl, *Wqh, *Wql, *Wkh, *Wkl, *Wph, *Wpl;
    bf16 *Qh, *Ql, *KVh, *KVl, *Oh, *Ol;
    cudaGetSymbolAddress((void**)&xh,  g_xh);  cudaGetSymbolAddress((void**)&xl,  g_xl);
    cudaGetSymbolAddress((void**)&Wqh, g_Wqh); cudaGetSymbolAddress((void**)&Wql, g_Wql);
    cudaGetSymbolAddress((void**)&Wkh, g_Wkh); cudaGetSymbolAddress((void**)&Wkl, g_Wkl);
    cudaGetSymbolAddress((void**)&Wph, g_Wph); cudaGetSymbolAddress((void**)&Wpl, g_Wpl);
    cudaGetSymbolAddress((void**)&Qh,  g_Qh);  cudaGetSymbolAddress((void**)&Ql,  g_Ql);
    cudaGetSymbolAddress((void**)&KVh, g_KVh); cudaGetSymbolAddress((void**)&KVl, g_KVl);
    cudaGetSymbolAddress((void**)&Oh,  g_Oh);  cudaGetSymbolAddress((void**)&Ol,  g_Ol);

    static bool attr_set = false;
    if (!attr_set) {
        cudaFuncSetAttribute(attn_mma_kernel,
                             cudaFuncAttributeMaxDynamicSharedMemorySize,
                             ATTN_SMEM_BYTES);
        attr_set = true;
    }

    // 0) split conversions (x + weights)
    cvt_split<<<(MROWS * DIM / 4) / 256, 256>>>(x, xh, xl);
    cvt_split<<<(DIM * DIM / 4) / 256, 256>>>(Wq, Wqh, Wql);
    cvt_split<<<(DIM * KVW / 4) / 256, 256>>>(Wkv, Wkh, Wkl);
    cvt_split<<<(DIM * DIM / 4) / 256, 256>>>(Wproj, Wph, Wpl);

    // 1) Q = (x @ Wq) * 0.125  -> split bf16
    {
        dim3 grid(DIM / 128, MROWS / 128);
        gemm_bf16<<<grid, 256>>>(xh, xl, Wqh, Wql, MROWS, DIM, DIM,
                                 nullptr, nullptr, Qh, Ql, ATT_SCALE);
    }
    // 2) KV = x @ Wkv -> split bf16
    {
        dim3 grid(KVW / 128, MROWS / 128);
        gemm_bf16<<<grid, 256>>>(xh, xl, Wkh, Wkl, MROWS, DIM, KVW,
                                 nullptr, nullptr, KVh, KVl, 1.0f);
    }
    // 3) tensor-core flash attention -> split bf16 O
    {
        dim3 grid(SEQ / 64, NHEAD, BATCH);
        attn_mma_kernel<<<grid, 128, ATTN_SMEM_BYTES>>>(Qh, Ql, KVh, KVl, Oh, Ol);
    }
    // 4) out = O @ Wproj + bproj (fp32)
    {
        dim3 grid(DIM / 128, MROWS / 128);
        gemm_bf16<<<grid, 256>>>(Oh, Ol, Wph, Wpl, MROWS, DIM, DIM,
                                 out, bproj, nullptr, nullptr, 1.0f);
    }
}

// round 8
// speedup vs baseline: 51.2056x; 1.0246x over previous
#include <cuda_runtime.h>
#include <cuda_bf16.h>
#include <math.h>
#include <stdint.h>

// Problem constants (Attention_146028888650)
#define BATCH 2
#define SEQ   2048
#define DIM   768
#define NHEAD 12
#define HDIM  64
#define KVW   128
#define MROWS (BATCH*SEQ)   // 4096
#define ATT_SCALE 0.125f

typedef __nv_bfloat16 bf16;

// ---------------- scratch (device globals, no runtime alloc) ----------------
__device__ bf16 g_xh [(size_t)MROWS * DIM];
__device__ bf16 g_xl [(size_t)MROWS * DIM];
__device__ bf16 g_Wqh[(size_t)DIM * DIM];
__device__ bf16 g_Wql[(size_t)DIM * DIM];
__device__ bf16 g_Wkh[(size_t)DIM * KVW];
__device__ bf16 g_Wkl[(size_t)DIM * KVW];
__device__ bf16 g_Wph[(size_t)DIM * DIM];
__device__ bf16 g_Wpl[(size_t)DIM * DIM];
__device__ bf16 g_Qh [(size_t)MROWS * DIM];
__device__ bf16 g_Ql [(size_t)MROWS * DIM];
__device__ bf16 g_KVh[(size_t)MROWS * KVW];
__device__ bf16 g_KVl[(size_t)MROWS * KVW];
__device__ bf16 g_Oh [(size_t)MROWS * DIM];
__device__ bf16 g_Ol [(size_t)MROWS * DIM];

// ---------------- helpers ----------------
__device__ __forceinline__ uint32_t pack2(float x, float y) {
    __nv_bfloat162 t = __float22bfloat162_rn(make_float2(x, y));
    return *reinterpret_cast<uint32_t*>(&t);
}
__device__ __forceinline__ float2 unpack2(uint32_t u) {
    __nv_bfloat162 t = *reinterpret_cast<__nv_bfloat162*>(&u);
    return __bfloat1622float2(t);
}
__device__ __forceinline__ uint32_t smem_addr(const void* p) {
    return (uint32_t)__cvta_generic_to_shared(p);
}
__device__ __forceinline__ void cp16(bf16* dst, const bf16* src) {
    asm volatile("cp.async.cg.shared.global [%0], [%1], 16;"
                 :: "r"(smem_addr(dst)), "l"(src));
}
#define CP_COMMIT()  asm volatile("cp.async.commit_group;" ::: "memory")
#define CP_WAIT(n)   asm volatile("cp.async.wait_group " #n ";" ::: "memory")

#define MMA_BF16(c, a, b)                                                        \
    asm volatile("mma.sync.aligned.m16n8k16.row.col.f32.bf16.bf16.f32 "          \
                 "{%0,%1,%2,%3},{%4,%5,%6,%7},{%8,%9},{%0,%1,%2,%3};"            \
                 : "+f"((c)[0]), "+f"((c)[1]), "+f"((c)[2]), "+f"((c)[3])        \
                 : "r"((a)[0]), "r"((a)[1]), "r"((a)[2]), "r"((a)[3]),           \
                   "r"((b)[0]), "r"((b)[1]))

#define LDSM_X4(r, addr)                                                         \
    asm volatile("ldmatrix.sync.aligned.m8n8.x4.shared.b16 {%0,%1,%2,%3}, [%4];" \
                 : "=r"((r)[0]), "=r"((r)[1]), "=r"((r)[2]), "=r"((r)[3])        \
                 : "r"(addr))
#define LDSM_X2(r, addr)                                                         \
    asm volatile("ldmatrix.sync.aligned.m8n8.x2.shared.b16 {%0,%1}, [%2];"       \
                 : "=r"((r)[0]), "=r"((r)[1]) : "r"(addr))
#define LDSM_X2T(r, addr)                                                        \
    asm volatile("ldmatrix.sync.aligned.m8n8.x2.trans.shared.b16 {%0,%1}, [%2];" \
                 : "=r"((r)[0]), "=r"((r)[1]) : "r"(addr))

// ---------------------------------------------------------------------------
// fp32 -> split bf16 (hi + lo)
// ---------------------------------------------------------------------------
__global__ void cvt_split(const float* __restrict__ src,
                          bf16* __restrict__ h, bf16* __restrict__ l)
{
    const int i = blockIdx.x * blockDim.x + threadIdx.x;
    float4 v = ((const float4*)src)[i];
    uint32_t h0 = pack2(v.x, v.y), h1 = pack2(v.z, v.w);
    float2 f0 = unpack2(h0), f1 = unpack2(h1);
    uint32_t l0 = pack2(v.x - f0.x, v.y - f0.y), l1 = pack2(v.z - f1.x, v.w - f1.y);
    ((uint2*)h)[i] = make_uint2(h0, h1);
    ((uint2*)l)[i] = make_uint2(l0, l1);
}

// ---------------------------------------------------------------------------
// Split-bf16 tensor-core GEMM (unchanged from round 7)
// ---------------------------------------------------------------------------
#define ASTR 40
#define BSTR 136

__global__ __launch_bounds__(256)
void gemm_bf16(const bf16* __restrict__ Ah, const bf16* __restrict__ Al,
               const bf16* __restrict__ Bh, const bf16* __restrict__ Bl,
               int M, int K, int N,
               float* __restrict__ Cf, const float* __restrict__ bias,
               bf16* __restrict__ Ch, bf16* __restrict__ Cl, float scale)
{
    __shared__ bf16 sAh[128 * ASTR];
    __shared__ bf16 sAl[128 * ASTR];
    __shared__ bf16 sBh[32 * BSTR];
    __shared__ bf16 sBl[32 * BSTR];

    const int tid  = threadIdx.x;
    const int lane = tid & 31;
    const int l16  = lane & 15;
    const int hi8  = (lane >> 4) * 8;
    const int w    = tid >> 5;
    const int wm   = w >> 2;
    const int wn   = w & 3;
    const int rowBlk = blockIdx.y * 128;
    const int colBlk = blockIdx.x * 128;

    const int aRow = tid >> 2;
    const int aCol = (tid & 3) * 8;
    const int bRow = tid >> 4;
    const int bCol = (tid & 15) * 8;

    #pragma unroll
    for (int i = 0; i < 2; ++i) {
        const int ar = aRow + i * 64;
        *(uint4*)(sAh + ar * ASTR + aCol) = *(const uint4*)(Ah + (size_t)(rowBlk + ar) * K + aCol);
        *(uint4*)(sAl + ar * ASTR + aCol) = *(const uint4*)(Al + (size_t)(rowBlk + ar) * K + aCol);
        const int br = bRow + i * 16;
        *(uint4*)(sBh + br * BSTR + bCol) = *(const uint4*)(Bh + (size_t)br * N + colBlk + bCol);
        *(uint4*)(sBl + br * BSTR + bCol) = *(const uint4*)(Bl + (size_t)br * N + colBlk + bCol);
    }
    __syncthreads();

    float acc[4][4][4] = {};
    uint4 pAh[2], pAl[2], pBh[2], pBl[2];

    const int nk = K / 32;
    for (int kt = 0; kt < nk; ++kt) {
        const bool more = (kt + 1 < nk);
        if (more) {
            const int k0 = (kt + 1) * 32;
            #pragma unroll
            for (int i = 0; i < 2; ++i) {
                const int ar = aRow + i * 64;
                pAh[i] = *(const uint4*)(Ah + (size_t)(rowBlk + ar) * K + k0 + aCol);
                pAl[i] = *(const uint4*)(Al + (size_t)(rowBlk + ar) * K + k0 + aCol);
                const int br = bRow + i * 16;
                pBh[i] = *(const uint4*)(Bh + (size_t)(k0 + br) * N + colBlk + bCol);
                pBl[i] = *(const uint4*)(Bl + (size_t)(k0 + br) * N + colBlk + bCol);
            }
        }

        #pragma unroll
        for (int s = 0; s < 2; ++s) {
            uint32_t bh[4][2], bl[4][2];
            #pragma unroll
            for (int nt = 0; nt < 4; ++nt) {
                const int boff = (s * 16 + l16) * BSTR + wn * 32 + nt * 8;
                LDSM_X2T(bh[nt], smem_addr(sBh + boff));
                LDSM_X2T(bl[nt], smem_addr(sBl + boff));
            }
            #pragma unroll
            for (int mt = 0; mt < 4; ++mt) {
                uint32_t ah[4], al[4];
                const int aoff = (wm * 64 + mt * 16 + l16) * ASTR + s * 16 + hi8;
                LDSM_X4(ah, smem_addr(sAh + aoff));
                LDSM_X4(al, smem_addr(sAl + aoff));
                #pragma unroll
                for (int nt = 0; nt < 4; ++nt) {
                    MMA_BF16(acc[mt][nt], ah, bh[nt]);
                    MMA_BF16(acc[mt][nt], ah, bl[nt]);
                    MMA_BF16(acc[mt][nt], al, bh[nt]);
                }
            }
        }

        if (more) {
            __syncthreads();
            #pragma unroll
            for (int i = 0; i < 2; ++i) {
                const int ar = aRow + i * 64;
                *(uint4*)(sAh + ar * ASTR + aCol) = pAh[i];
                *(uint4*)(sAl + ar * ASTR + aCol) = pAl[i];
                const int br = bRow + i * 16;
                *(uint4*)(sBh + br * BSTR + bCol) = pBh[i];
                *(uint4*)(sBl + br * BSTR + bCol) = pBl[i];
            }
            __syncthreads();
        }
    }

    const int rBase = rowBlk + wm * 64 + (lane >> 2);
    const int cBase = colBlk + wn * 32 + (lane & 3) * 2;
    #pragma unroll
    for (int mt = 0; mt < 4; ++mt) {
        const int r0 = rBase + mt * 16;
        const int r1 = r0 + 8;
        #pragma unroll
        for (int nt = 0; nt < 4; ++nt) {
            const int c = cBase + nt * 8;
            float v00 = acc[mt][nt][0], v01 = acc[mt][nt][1];
            float v10 = acc[mt][nt][2], v11 = acc[mt][nt][3];
            if (Cf) {
                const float b0 = bias ? bias[c] : 0.f;
                const float b1 = bias ? bias[c + 1] : 0.f;
                *(float2*)(Cf + (size_t)r0 * N + c) = make_float2(v00 + b0, v01 + b1);
                *(float2*)(Cf + (size_t)r1 * N + c) = make_float2(v10 + b0, v11 + b1);
            } else {
                v00 *= scale; v01 *= scale; v10 *= scale; v11 *= scale;
                uint32_t h0 = pack2(v00, v01);
                float2 f0 = unpack2(h0);
                uint32_t l0 = pack2(v00 - f0.x, v01 - f0.y);
                uint32_t h1 = pack2(v10, v11);
                float2 f1 = unpack2(h1);
                uint32_t l1 = pack2(v10 - f1.x, v11 - f1.y);
                *(uint32_t*)(Ch + (size_t)r0 * N + c) = h0;
                *(uint32_t*)(Cl + (size_t)r0 * N + c) = l0;
                *(uint32_t*)(Ch + (size_t)r1 * N + c) = h1;
                *(uint32_t*)(Cl + (size_t)r1 * N + c) = l1;
            }
        }
    }
}

// ---------------------------------------------------------------------------
// Tensor-core flash attention v2: 128q x 64k tiles, 8 warps,
// cp.async double-buffered K/V, split-bf16 mma.
// smem layout (bf16 units, LSTR=72):
//   Qh[128*72]@0, Ql[128*72]@9216,
//   2 stages @18432 + s*18432: {Kh@0, Kl@4608, Vh@9216, Vl@13824}
// total = 55296 bf16 = 110592 B
// ---------------------------------------------------------------------------
#define LSTR 72
#define SQH  0
#define SQL  9216
#define STG0 18432
#define STG_SZ 18432
#define ATTN_SMEM_BYTES (55296 * 2)

__global__ __launch_bounds__(256)
void attn_mma_kernel(const bf16* __restrict__ Qh, const bf16* __restrict__ Ql,
                     const bf16* __restrict__ KVh, const bf16* __restrict__ KVl,
                     bf16* __restrict__ Oh, bf16* __restrict__ Ol)
{
    extern __shared__ bf16 sm[];

    const int tid  = threadIdx.x;
    const int lane = tid & 31;
    const int w    = tid >> 5;       // 0..7, rows w*16..w*16+15
    const int qBase = blockIdx.x * 128;
    const int h     = blockIdx.y;
    const int b     = blockIdx.z;

    const bf16* gkvh = KVh + (size_t)b * SEQ * KVW;
    const bf16* gkvl = KVl + (size_t)b * SEQ * KVW;

    // K/V stage loader: 4 arrays x 64 rows x 8 uint4; 2 cp.async x 4 per thread
    const int kvRow0 = tid >> 3;            // 0..31
    const int kvC    = (tid & 7) * 8;
    auto issue_kv = [&](int kt, bf16* base) {
        #pragma unroll
        for (int j = 0; j < 2; ++j) {
            const int row = kvRow0 + j * 32;
            const size_t g = (size_t)(kt * 64 + row) * KVW + kvC;
            bf16* d = base + row * LSTR + kvC;
            cp16(d,                gkvh + g);
            cp16(d + 4608,         gkvl + g);
            cp16(d + 9216,         gkvh + g + HDIM);
            cp16(d + 13824,        gkvl + g + HDIM);
        }
    };

    // stage 0 in flight first
    issue_kv(0, sm + STG0);
    CP_COMMIT();

    // Load Q tile (128 x 64), hi+lo (regular loads, overlap with cp.async)
    {
        const bf16* gqh = Qh + (size_t)(b * SEQ + qBase) * DIM + h * HDIM;
        const bf16* gql = Ql + (size_t)(b * SEQ + qBase) * DIM + h * HDIM;
        #pragma unroll
        for (int j = 0; j < 4; ++j) {
            const int idx = tid + j * 256;      // 0..1023
            const int row = idx >> 3;
            const int c   = (idx & 7) * 8;
            *(uint4*)(sm + SQH + row * LSTR + c) = *(const uint4*)(gqh + (size_t)row * DIM + c);
            *(uint4*)(sm + SQL + row * LSTR + c) = *(const uint4*)(gql + (size_t)row * DIM + c);
        }
    }

    float oc[8][4] = {};
    float m0 = -1e30f, m1 = -1e30f, l0 = 0.f, l1 = 0.f;

    const int l16 = lane & 15;
    const int aRow = w * 16 + l16;
    const int aColBase = (lane >> 4) * 8;
    const int bRowOff = l16 & 7;
    const int bColOff = (l16 >> 3) * 8;

    const int NK = SEQ / 64;   // 32
    for (int kt = 0; kt < NK; ++kt) {
        bf16* cur = sm + STG0 + (kt & 1) * STG_SZ;
        if (kt + 1 < NK) {
            issue_kv(kt + 1, sm + STG0 + ((kt + 1) & 1) * STG_SZ);
            CP_COMMIT();
            CP_WAIT(1);
        } else {
            CP_WAIT(0);
        }
        __syncthreads();

        bf16* sKh = cur;
        bf16* sKl = cur + 4608;
        bf16* sVh = cur + 9216;
        bf16* sVl = cur + 13824;

        // ---- S = Q K^T (hh + hl + lh) ----
        float sc[8][4] = {};
        #pragma unroll
        for (int ks = 0; ks < 4; ++ks) {
            uint32_t aqh[4], aql[4];
            LDSM_X4(aqh, smem_addr(sm + SQH + aRow * LSTR + ks * 16 + aColBase));
            LDSM_X4(aql, smem_addr(sm + SQL + aRow * LSTR + ks * 16 + aColBase));
            #pragma unroll
            for (int nt = 0; nt < 8; ++nt) {
                uint32_t bkh[2], bkl[2];
                const int boff = (nt * 8 + bRowOff) * LSTR + ks * 16 + bColOff;
                LDSM_X2(bkh, smem_addr(sKh + boff));
                LDSM_X2(bkl, smem_addr(sKl + boff));
                MMA_BF16(sc[nt], aqh, bkh);
                MMA_BF16(sc[nt], aqh, bkl);
                MMA_BF16(sc[nt], aql, bkh);
            }
        }

        // ---- online softmax ----
        float mx0 = -1e30f, mx1 = -1e30f;
        #pragma unroll
        for (int nt = 0; nt < 8; ++nt) {
            mx0 = fmaxf(mx0, fmaxf(sc[nt][0], sc[nt][1]));
            mx1 = fmaxf(mx1, fmaxf(sc[nt][2], sc[nt][3]));
        }
        mx0 = fmaxf(mx0, __shfl_xor_sync(0xffffffffu, mx0, 1));
        mx0 = fmaxf(mx0, __shfl_xor_sync(0xffffffffu, mx0, 2));
        mx1 = fmaxf(mx1, __shfl_xor_sync(0xffffffffu, mx1, 1));
        mx1 = fmaxf(mx1, __shfl_xor_sync(0xffffffffu, mx1, 2));
        const float mn0 = fmaxf(m0, mx0);
        const float mn1 = fmaxf(m1, mx1);
        const float cr0 = __expf(m0 - mn0);
        const float cr1 = __expf(m1 - mn1);
        m0 = mn0; m1 = mn1;

        float s0 = 0.f, s1 = 0.f;
        #pragma unroll
        for (int nt = 0; nt < 8; ++nt) {
            sc[nt][0] = __expf(sc[nt][0] - mn0);
            sc[nt][1] = __expf(sc[nt][1] - mn0);
            sc[nt][2] = __expf(sc[nt][2] - mn1);
            sc[nt][3] = __expf(sc[nt][3] - mn1);
            s0 += sc[nt][0] + sc[nt][1];
            s1 += sc[nt][2] + sc[nt][3];
        }
        s0 += __shfl_xor_sync(0xffffffffu, s0, 1);
        s0 += __shfl_xor_sync(0xffffffffu, s0, 2);
        s1 += __shfl_xor_sync(0xffffffffu, s1, 1);
        s1 += __shfl_xor_sync(0xffffffffu, s1, 2);
        l0 = l0 * cr0 + s0;
        l1 = l1 * cr1 + s1;
        #pragma unroll
        for (int dt = 0; dt < 8; ++dt) {
            oc[dt][0] *= cr0; oc[dt][1] *= cr0;
            oc[dt][2] *= cr1; oc[dt][3] *= cr1;
        }

        // ---- O += P V (split bf16) ----
        #pragma unroll
        for (int g = 0; g < 4; ++g) {
            const int t0 = 2 * g, t1 = 2 * g + 1;
            uint32_t ah[4], al[4];
            ah[0] = pack2(sc[t0][0], sc[t0][1]);
            ah[1] = pack2(sc[t0][2], sc[t0][3]);
            ah[2] = pack2(sc[t1][0], sc[t1][1]);
            ah[3] = pack2(sc[t1][2], sc[t1][3]);
            {
                float2 f;
                f = unpack2(ah[0]); al[0] = pack2(sc[t0][0] - f.x, sc[t0][1] - f.y);
                f = unpack2(ah[1]); al[1] = pack2(sc[t0][2] - f.x, sc[t0][3] - f.y);
                f = unpack2(ah[2]); al[2] = pack2(sc[t1][0] - f.x, sc[t1][1] - f.y);
                f = unpack2(ah[3]); al[3] = pack2(sc[t1][2] - f.x, sc[t1][3] - f.y);
            }
            #pragma unroll
            for (int dt = 0; dt < 8; ++dt) {
                uint32_t bvh[2], bvl[2];
                const int voff = (g * 16 + l16) * LSTR + dt * 8;
                LDSM_X2T(bvh, smem_addr(sVh + voff));
                LDSM_X2T(bvl, smem_addr(sVl + voff));
                MMA_BF16(oc[dt], ah, bvh);
                MMA_BF16(oc[dt], ah, bvl);
                MMA_BF16(oc[dt], al, bvh);
            }
        }
        __syncthreads();   // all warps done with cur before it is overwritten
    }

    // ---- normalize + split-bf16 store ----
    const float inv0 = 1.f / l0;
    const float inv1 = 1.f / l1;
    const int r0 = w * 16 + (lane >> 2);
    const int r1 = r0 + 8;
    const size_t base0 = (size_t)(b * SEQ + qBase + r0) * DIM + h * HDIM;
    const size_t base1 = (size_t)(b * SEQ + qBase + r1) * DIM + h * HDIM;
    #pragma unroll
    for (int dt = 0; dt < 8; ++dt) {
        const int col = dt * 8 + (lane & 3) * 2;
        const float v00 = oc[dt][0] * inv0, v01 = oc[dt][1] * inv0;
        const float v10 = oc[dt][2] * inv1, v11 = oc[dt][3] * inv1;
        uint32_t h0 = pack2(v00, v01);
        float2 f0 = unpack2(h0);
        uint32_t l0w = pack2(v00 - f0.x, v01 - f0.y);
        uint32_t h1 = pack2(v10, v11);
        float2 f1 = unpack2(h1);
        uint32_t l1w = pack2(v10 - f1.x, v11 - f1.y);
        *(uint32_t*)(Oh + base0 + col) = h0;
        *(uint32_t*)(Ol + base0 + col) = l0w;
        *(uint32_t*)(Oh + base1 + col) = h1;
        *(uint32_t*)(Ol + base1 + col) = l1w;
    }
}

// ---------------------------------------------------------------------------
extern "C" void kernel_launch(void* const* d_in, const int* in_sizes, int n_in,
                              void* d_out, int out_size)
{
    const float* x     = (const float*)d_in[0];
    const float* Wq    = (const float*)d_in[1];
    const float* Wkv   = (const float*)d_in[2];
    const float* Wproj = (const float*)d_in[3];
    const float* bproj = (const float*)d_in[4];
    float* out = (float*)d_out;

    bf16 *xh, *xl, *Wqh, *Wql, *Wkh, *Wkl, *Wph, *Wpl;
    bf16 *Qh, *Ql, *KVh, *KVl, *Oh, *Ol;
    cudaGetSymbolAddress((void**)&xh,  g_xh);  cudaGetSymbolAddress((void**)&xl,  g_xl);
    cudaGetSymbolAddress((void**)&Wqh, g_Wqh); cudaGetSymbolAddress((void**)&Wql, g_Wql);
    cudaGetSymbolAddress((void**)&Wkh, g_Wkh); cudaGetSymbolAddress((void**)&Wkl, g_Wkl);
    cudaGetSymbolAddress((void**)&Wph, g_Wph); cudaGetSymbolAddress((void**)&Wpl, g_Wpl);
    cudaGetSymbolAddress((void**)&Qh,  g_Qh);  cudaGetSymbolAddress((void**)&Ql,  g_Ql);
    cudaGetSymbolAddress((void**)&KVh, g_KVh); cudaGetSymbolAddress((void**)&KVl, g_KVl);
    cudaGetSymbolAddress((void**)&Oh,  g_Oh);  cudaGetSymbolAddress((void**)&Ol,  g_Ol);

    static bool attr_set = false;
    if (!attr_set) {
        cudaFuncSetAttribute(attn_mma_kernel,
                             cudaFuncAttributeMaxDynamicSharedMemorySize,
                             ATTN_SMEM_BYTES);
        attr_set = true;
    }

    // 0) split conversions (x + weights)
    cvt_split<<<(MROWS * DIM / 4) / 256, 256>>>(x, xh, xl);
    cvt_split<<<(DIM * DIM / 4) / 256, 256>>>(Wq, Wqh, Wql);
    cvt_split<<<(DIM * KVW / 4) / 256, 256>>>(Wkv, Wkh, Wkl);
    cvt_split<<<(DIM * DIM / 4) / 256, 256>>>(Wproj, Wph, Wpl);

    // 1) Q = (x @ Wq) * 0.125 -> split bf16
    {
        dim3 grid(DIM / 128, MROWS / 128);
        gemm_bf16<<<grid, 256>>>(xh, xl, Wqh, Wql, MROWS, DIM, DIM,
                                 nullptr, nullptr, Qh, Ql, ATT_SCALE);
    }
    // 2) KV = x @ Wkv -> split bf16
    {
        dim3 grid(KVW / 128, MROWS / 128);
        gemm_bf16<<<grid, 256>>>(xh, xl, Wkh, Wkl, MROWS, DIM, KVW,
                                 nullptr, nullptr, KVh, KVl, 1.0f);
    }
    // 3) tensor-core flash attention -> split bf16 O
    {
        dim3 grid(SEQ / 128, NHEAD, BATCH);
        attn_mma_kernel<<<grid, 256, ATTN_SMEM_BYTES>>>(Qh, Ql, KVh, KVl, Oh, Ol);
    }
    // 4) out = O @ Wproj + bproj (fp32)
    {
        dim3 grid(DIM / 128, MROWS / 128);
        gemm_bf16<<<grid, 256>>>(Oh, Ol, Wph, Wpl, MROWS, DIM, DIM,
                                 out, bproj, nullptr, nullptr, 1.0f);
    }
}

// round 12
// speedup vs baseline: 56.7769x; 1.1088x over previous
#include <cuda_runtime.h>
#include <cuda_bf16.h>
#include <math.h>
#include <stdint.h>

#define BATCH 2
#define SEQ   2048
#define DIM   768
#define NHEAD 12
#define HDIM  64
#define KVW   128
#define MROWS (BATCH*SEQ)
#define ATT_SCALE 0.125f

typedef __nv_bfloat16 bf16;

// ---------------- scratch ----------------
__device__ bf16 g_xh [(size_t)MROWS * DIM];
__device__ bf16 g_xl [(size_t)MROWS * DIM];
__device__ bf16 g_Wqh[(size_t)DIM * DIM];
__device__ bf16 g_Wql[(size_t)DIM * DIM];
__device__ bf16 g_Wkh[(size_t)DIM * KVW];
__device__ bf16 g_Wkl[(size_t)DIM * KVW];
__device__ bf16 g_Wph[(size_t)DIM * DIM];
__device__ bf16 g_Wpl[(size_t)DIM * DIM];
__device__ bf16 g_Qh [(size_t)MROWS * DIM];
__device__ bf16 g_Ql [(size_t)MROWS * DIM];
__device__ bf16 g_KVh[(size_t)MROWS * KVW];
__device__ bf16 g_KVl[(size_t)MROWS * KVW];
__device__ bf16 g_Oh [(size_t)MROWS * DIM];
__device__ bf16 g_Ol [(size_t)MROWS * DIM];

// ---------------- helpers ----------------
__device__ __forceinline__ uint32_t pack2(float x, float y) {
    __nv_bfloat162 t = __float22bfloat162_rn(make_float2(x, y));
    return *reinterpret_cast<uint32_t*>(&t);
}
__device__ __forceinline__ float2 unpack2(uint32_t u) {
    __nv_bfloat162 t = *reinterpret_cast<__nv_bfloat162*>(&u);
    return __bfloat1622float2(t);
}
__device__ __forceinline__ uint32_t smem_addr(const void* p) {
    return (uint32_t)__cvta_generic_to_shared(p);
}
__device__ __forceinline__ void cp16(bf16* dst, const bf16* src) {
    asm volatile("cp.async.cg.shared.global [%0], [%1], 16;"
                 :: "r"(smem_addr(dst)), "l"(src));
}
#define CP_COMMIT()  asm volatile("cp.async.commit_group;" ::: "memory")
#define CP_WAIT(n)   asm volatile("cp.async.wait_group " #n ";" ::: "memory")

#define MMA_BF16(c, a, b0, b1)                                                   \
    asm volatile("mma.sync.aligned.m16n8k16.row.col.f32.bf16.bf16.f32 "          \
                 "{%0,%1,%2,%3},{%4,%5,%6,%7},{%8,%9},{%0,%1,%2,%3};"            \
                 : "+f"((c)[0]), "+f"((c)[1]), "+f"((c)[2]), "+f"((c)[3])        \
                 : "r"((a)[0]), "r"((a)[1]), "r"((a)[2]), "r"((a)[3]),           \
                   "r"(b0), "r"(b1))

#define LDSM_X4(r, addr)                                                         \
    asm volatile("ldmatrix.sync.aligned.m8n8.x4.shared.b16 {%0,%1,%2,%3}, [%4];" \
                 : "=r"((r)[0]), "=r"((r)[1]), "=r"((r)[2]), "=r"((r)[3])        \
                 : "r"(addr))
#define LDSM_X4T(r, addr)                                                        \
    asm volatile("ldmatrix.sync.aligned.m8n8.x4.trans.shared.b16 {%0,%1,%2,%3}, [%4];" \
                 : "=r"((r)[0]), "=r"((r)[1]), "=r"((r)[2]), "=r"((r)[3])        \
                 : "r"(addr))
#define LDSM_X2T(r, addr)                                                        \
    asm volatile("ldmatrix.sync.aligned.m8n8.x2.trans.shared.b16 {%0,%1}, [%2];" \
                 : "=r"((r)[0]), "=r"((r)[1]) : "r"(addr))

// ---------------------------------------------------------------------------
// Fused fp32 -> split bf16 for all 4 tensors in one launch.
// Regions (float4 units): x 786432 | Wq 147456 | Wkv 24576 | Wproj 147456
// ---------------------------------------------------------------------------
#define X4SZ 786432
#define Q4SZ 147456
#define K4SZ 24576
#define CVT_TOTAL (X4SZ + Q4SZ + K4SZ + Q4SZ)   // 1105920

__global__ void cvt_all(const float* __restrict__ x,  const float* __restrict__ Wq,
                        const float* __restrict__ Wkv, const float* __restrict__ Wp,
                        bf16* __restrict__ xh,  bf16* __restrict__ xl,
                        bf16* __restrict__ Wqh, bf16* __restrict__ Wql,
                        bf16* __restrict__ Wkh, bf16* __restrict__ Wkl,
                        bf16* __restrict__ Wph, bf16* __restrict__ Wpl)
{
    int i = blockIdx.x * blockDim.x + threadIdx.x;
    const float* src; bf16 *h, *l; int j = i;
    if (j < X4SZ) { src = x; h = xh; l = xl; }
    else {
        j -= X4SZ;
        if (j < Q4SZ) { src = Wq; h = Wqh; l = Wql; }
        else {
            j -= Q4SZ;
            if (j < K4SZ) { src = Wkv; h = Wkh; l = Wkl; }
            else { j -= K4SZ; src = Wp; h = Wph; l = Wpl; }
        }
    }
    float4 v = ((const float4*)src)[j];
    uint32_t h0 = pack2(v.x, v.y), h1 = pack2(v.z, v.w);
    float2 f0 = unpack2(h0), f1 = unpack2(h1);
    uint32_t l0 = pack2(v.x - f0.x, v.y - f0.y), l1 = pack2(v.z - f1.x, v.w - f1.y);
    ((uint2*)h)[j] = make_uint2(h0, h1);
    ((uint2*)l)[j] = make_uint2(l0, l1);
}

// ---------------------------------------------------------------------------
// Split-bf16 GEMM with two column-partitioned B matrices.
// C[:, 0:N1] = A*B1 ; C[:, N1:N1+N2] = A*B2 (N2 may be 0).
// Epilogue: fp32+bias to Cf (stride N1) OR split-bf16 to (C1,scale1)/(C2,scale2).
// ---------------------------------------------------------------------------
#define ASTR 40
#define BSTR 136

__global__ __launch_bounds__(256)
void gemm_bf16(const bf16* __restrict__ Ah, const bf16* __restrict__ Al,
               const bf16* __restrict__ B1h, const bf16* __restrict__ B1l, int N1,
               const bf16* __restrict__ B2h, const bf16* __restrict__ B2l, int N2,
               int M, int K,
               float* __restrict__ Cf, const float* __restrict__ bias,
               bf16* __restrict__ C1h, bf16* __restrict__ C1l, float scale1,
               bf16* __restrict__ C2h, bf16* __restrict__ C2l, float scale2)
{
    __shared__ bf16 sAh[128 * ASTR];
    __shared__ bf16 sAl[128 * ASTR];
    __shared__ bf16 sBh[32 * BSTR];
    __shared__ bf16 sBl[32 * BSTR];

    const int tid  = threadIdx.x;
    const int lane = tid & 31;
    const int l16  = lane & 15;
    const int hi8  = (lane >> 4) * 8;
    const int w    = tid >> 5;
    const int wm   = w >> 2;
    const int wn   = w & 3;
    const int rowBlk = blockIdx.y * 128;
    const int colBlk = blockIdx.x * 128;

    const bool isB2 = (colBlk >= N1);
    const bf16* Bh = isB2 ? B2h : B1h;
    const bf16* Bl = isB2 ? B2l : B1l;
    const int   NB = isB2 ? N2 : N1;
    const int   cB = colBlk - (isB2 ? N1 : 0);

    const int aRow = tid >> 2;
    const int aCol = (tid & 3) * 8;
    const int bRow = tid >> 4;
    const int bCol = (tid & 15) * 8;

    #pragma unroll
    for (int i = 0; i < 2; ++i) {
        const int ar = aRow + i * 64;
        *(uint4*)(sAh + ar * ASTR + aCol) = *(const uint4*)(Ah + (size_t)(rowBlk + ar) * K + aCol);
        *(uint4*)(sAl + ar * ASTR + aCol) = *(const uint4*)(Al + (size_t)(rowBlk + ar) * K + aCol);
        const int br = bRow + i * 16;
        *(uint4*)(sBh + br * BSTR + bCol) = *(const uint4*)(Bh + (size_t)br * NB + cB + bCol);
        *(uint4*)(sBl + br * BSTR + bCol) = *(const uint4*)(Bl + (size_t)br * NB + cB + bCol);
    }
    __syncthreads();

    float acc[4][4][4] = {};
    uint4 pAh[2], pAl[2], pBh[2], pBl[2];

    const int nk = K / 32;
    for (int kt = 0; kt < nk; ++kt) {
        const bool more = (kt + 1 < nk);
        if (more) {
            const int k0 = (kt + 1) * 32;
            #pragma unroll
            for (int i = 0; i < 2; ++i) {
                const int ar = aRow + i * 64;
                pAh[i] = *(const uint4*)(Ah + (size_t)(rowBlk + ar) * K + k0 + aCol);
                pAl[i] = *(const uint4*)(Al + (size_t)(rowBlk + ar) * K + k0 + aCol);
                const int br = bRow + i * 16;
                pBh[i] = *(const uint4*)(Bh + (size_t)(k0 + br) * NB + cB + bCol);
                pBl[i] = *(const uint4*)(Bl + (size_t)(k0 + br) * NB + cB + bCol);
            }
        }

        #pragma unroll
        for (int s = 0; s < 2; ++s) {
            uint32_t bh[4][2], bl[4][2];
            #pragma unroll
            for (int nt = 0; nt < 4; ++nt) {
                const int boff = (s * 16 + l16) * BSTR + wn * 32 + nt * 8;
                LDSM_X2T(bh[nt], smem_addr(sBh + boff));
                LDSM_X2T(bl[nt], smem_addr(sBl + boff));
            }
            #pragma unroll
            for (int mt = 0; mt < 4; ++mt) {
                uint32_t ah[4], al[4];
                const int aoff = (wm * 64 + mt * 16 + l16) * ASTR + s * 16 + hi8;
                LDSM_X4(ah, smem_addr(sAh + aoff));
                LDSM_X4(al, smem_addr(sAl + aoff));
                #pragma unroll
                for (int nt = 0; nt < 4; ++nt) {
                    MMA_BF16(acc[mt][nt], ah, bh[nt][0], bh[nt][1]);
                    MMA_BF16(acc[mt][nt], ah, bl[nt][0], bl[nt][1]);
                    MMA_BF16(acc[mt][nt], al, bh[nt][0], bh[nt][1]);
                }
            }
        }

        if (more) {
            __syncthreads();
            #pragma unroll
            for (int i = 0; i < 2; ++i) {
                const int ar = aRow + i * 64;
                *(uint4*)(sAh + ar * ASTR + aCol) = pAh[i];
                *(uint4*)(sAl + ar * ASTR + aCol) = pAl[i];
                const int br = bRow + i * 16;
                *(uint4*)(sBh + br * BSTR + bCol) = pBh[i];
                *(uint4*)(sBl + br * BSTR + bCol) = pBl[i];
            }
            __syncthreads();
        }
    }

    bf16* Ch = isB2 ? C2h : C1h;
    bf16* Cl = isB2 ? C2l : C1l;
    const float scale = isB2 ? scale2 : scale1;

    const int rBase = rowBlk + wm * 64 + (lane >> 2);
    const int cLoc  = cB + wn * 32 + (lane & 3) * 2;
    #pragma unroll
    for (int mt = 0; mt < 4; ++mt) {
        const int r0 = rBase + mt * 16;
        const int r1 = r0 + 8;
        #pragma unroll
        for (int nt = 0; nt < 4; ++nt) {
            const int c = cLoc + nt * 8;
            float v00 = acc[mt][nt][0], v01 = acc[mt][nt][1];
            float v10 = acc[mt][nt][2], v11 = acc[mt][nt][3];
            if (Cf) {
                const float b0 = bias ? bias[c] : 0.f;
                const float b1 = bias ? bias[c + 1] : 0.f;
                *(float2*)(Cf + (size_t)r0 * N1 + c) = make_float2(v00 + b0, v01 + b1);
                *(float2*)(Cf + (size_t)r1 * N1 + c) = make_float2(v10 + b0, v11 + b1);
            } else {
                v00 *= scale; v01 *= scale; v10 *= scale; v11 *= scale;
                uint32_t h0 = pack2(v00, v01);
                float2 f0 = unpack2(h0);
                uint32_t l0 = pack2(v00 - f0.x, v01 - f0.y);
                uint32_t h1 = pack2(v10, v11);
                float2 f1 = unpack2(h1);
                uint32_t l1 = pack2(v10 - f1.x, v11 - f1.y);
                *(uint32_t*)(Ch + (size_t)r0 * NB + c) = h0;
                *(uint32_t*)(Cl + (size_t)r0 * NB + c) = l0;
                *(uint32_t*)(Ch + (size_t)r1 * NB + c) = h1;
                *(uint32_t*)(Cl + (size_t)r1 * NB + c) = l1;
            }
        }
    }
}

// ---------------------------------------------------------------------------
// Flash attention v3: 128q x 64k, 8 warps, cp.async double buffer,
// x4 ldmatrix for K and V fragment loads (halved LDSM issue).
// ---------------------------------------------------------------------------
#define LSTR 72
#define SQH  0
#define SQL  9216
#define STG0 18432
#define STG_SZ 18432
#define ATTN_SMEM_BYTES (55296 * 2)

__global__ __launch_bounds__(256)
void attn_mma_kernel(const bf16* __restrict__ Qh, const bf16* __restrict__ Ql,
                     const bf16* __restrict__ KVh, const bf16* __restrict__ KVl,
                     bf16* __restrict__ Oh, bf16* __restrict__ Ol)
{
    extern __shared__ bf16 sm[];

    const int tid  = threadIdx.x;
    const int lane = tid & 31;
    const int w    = tid >> 5;
    const int qBase = blockIdx.x * 128;
    const int h     = blockIdx.y;
    const int b     = blockIdx.z;

    const bf16* gkvh = KVh + (size_t)b * SEQ * KVW;
    const bf16* gkvl = KVl + (size_t)b * SEQ * KVW;

    const int kvRow0 = tid >> 3;
    const int kvC    = (tid & 7) * 8;
    auto issue_kv = [&](int kt, bf16* base) {
        #pragma unroll
        for (int j = 0; j < 2; ++j) {
            const int row = kvRow0 + j * 32;
            const size_t g = (size_t)(kt * 64 + row) * KVW + kvC;
            bf16* d = base + row * LSTR + kvC;
            cp16(d,         gkvh + g);
            cp16(d + 4608,  gkvl + g);
            cp16(d + 9216,  gkvh + g + HDIM);
            cp16(d + 13824, gkvl + g + HDIM);
        }
    };

    issue_kv(0, sm + STG0);
    CP_COMMIT();

    {
        const bf16* gqh = Qh + (size_t)(b * SEQ + qBase) * DIM + h * HDIM;
        const bf16* gql = Ql + (size_t)(b * SEQ + qBase) * DIM + h * HDIM;
        #pragma unroll
        for (int j = 0; j < 4; ++j) {
            const int idx = tid + j * 256;
            const int row = idx >> 3;
            const int c   = (idx & 7) * 8;
            *(uint4*)(sm + SQH + row * LSTR + c) = *(const uint4*)(gqh + (size_t)row * DIM + c);
            *(uint4*)(sm + SQL + row * LSTR + c) = *(const uint4*)(gql + (size_t)row * DIM + c);
        }
    }

    float oc[8][4] = {};
    float m0 = -1e30f, m1 = -1e30f, l0 = 0.f, l1 = 0.f;

    const int l16 = lane & 15;
    // Q (A-operand) addressing
    const int aRow = w * 16 + l16;
    const int aColBase = (lane >> 4) * 8;
    // K x4 addressing: two n-tiles per load
    const int kRowOff = (l16 & 7) + ((lane >> 4) << 3);
    const int kColOff = ((l16 >> 3) & 1) * 8;
    // V x4-trans addressing: two n-tiles (dt) per load
    const int vRow = l16;
    const int vColOff = (lane >> 4) * 8;

    const int NK = SEQ / 64;
    for (int kt = 0; kt < NK; ++kt) {
        bf16* cur = sm + STG0 + (kt & 1) * STG_SZ;
        if (kt + 1 < NK) {
            issue_kv(kt + 1, sm + STG0 + ((kt + 1) & 1) * STG_SZ);
            CP_COMMIT();
            CP_WAIT(1);
        } else {
            CP_WAIT(0);
        }
        __syncthreads();

        bf16* sKh = cur;
        bf16* sKl = cur + 4608;
        bf16* sVh = cur + 9216;
        bf16* sVl = cur + 13824;

        // ---- S = Q K^T ----
        float sc[8][4] = {};
        #pragma unroll
        for (int ks = 0; ks < 4; ++ks) {
            uint32_t aqh[4], aql[4];
            LDSM_X4(aqh, smem_addr(sm + SQH + aRow * LSTR + ks * 16 + aColBase));
            LDSM_X4(aql, smem_addr(sm + SQL + aRow * LSTR + ks * 16 + aColBase));
            #pragma unroll
            for (int ntp = 0; ntp < 4; ++ntp) {
                uint32_t bkh[4], bkl[4];
                const int boff = (ntp * 16 + kRowOff) * LSTR + ks * 16 + kColOff;
                LDSM_X4(bkh, smem_addr(sKh + boff));
                LDSM_X4(bkl, smem_addr(sKl + boff));
                MMA_BF16(sc[2*ntp],   aqh, bkh[0], bkh[1]);
                MMA_BF16(sc[2*ntp],   aqh, bkl[0], bkl[1]);
                MMA_BF16(sc[2*ntp],   aql, bkh[0], bkh[1]);
                MMA_BF16(sc[2*ntp+1], aqh, bkh[2], bkh[3]);
                MMA_BF16(sc[2*ntp+1], aqh, bkl[2], bkl[3]);
                MMA_BF16(sc[2*ntp+1], aql, bkh[2], bkh[3]);
            }
        }

        // ---- online softmax ----
        float mx0 = -1e30f, mx1 = -1e30f;
        #pragma unroll
        for (int nt = 0; nt < 8; ++nt) {
            mx0 = fmaxf(mx0, fmaxf(sc[nt][0], sc[nt][1]));
            mx1 = fmaxf(mx1, fmaxf(sc[nt][2], sc[nt][3]));
        }
        mx0 = fmaxf(mx0, __shfl_xor_sync(0xffffffffu, mx0, 1));
        mx0 = fmaxf(mx0, __shfl_xor_sync(0xffffffffu, mx0, 2));
        mx1 = fmaxf(mx1, __shfl_xor_sync(0xffffffffu, mx1, 1));
        mx1 = fmaxf(mx1, __shfl_xor_sync(0xffffffffu, mx1, 2));
        const float mn0 = fmaxf(m0, mx0);
        const float mn1 = fmaxf(m1, mx1);
        const float cr0 = __expf(m0 - mn0);
        const float cr1 = __expf(m1 - mn1);
        m0 = mn0; m1 = mn1;

        float s0 = 0.f, s1 = 0.f;
        #pragma unroll
        for (int nt = 0; nt < 8; ++nt) {
            sc[nt][0] = __expf(sc[nt][0] - mn0);
            sc[nt][1] = __expf(sc[nt][1] - mn0);
            sc[nt][2] = __expf(sc[nt][2] - mn1);
            sc[nt][3] = __expf(sc[nt][3] - mn1);
            s0 += sc[nt][0] + sc[nt][1];
            s1 += sc[nt][2] + sc[nt][3];
        }
        s0 += __shfl_xor_sync(0xffffffffu, s0, 1);
        s0 += __shfl_xor_sync(0xffffffffu, s0, 2);
        s1 += __shfl_xor_sync(0xffffffffu, s1, 1);
        s1 += __shfl_xor_sync(0xffffffffu, s1, 2);
        l0 = l0 * cr0 + s0;
        l1 = l1 * cr1 + s1;
        #pragma unroll
        for (int dt = 0; dt < 8; ++dt) {
            oc[dt][0] *= cr0; oc[dt][1] *= cr0;
            oc[dt][2] *= cr1; oc[dt][3] *= cr1;
        }

        // ---- O += P V ----
        #pragma unroll
        for (int g = 0; g < 4; ++g) {
            const int t0 = 2 * g, t1 = 2 * g + 1;
            uint32_t ah[4], al[4];
            ah[0] = pack2(sc[t0][0], sc[t0][1]);
            ah[1] = pack2(sc[t0][2], sc[t0][3]);
            ah[2] = pack2(sc[t1][0], sc[t1][1]);
            ah[3] = pack2(sc[t1][2], sc[t1][3]);
            {
                float2 f;
                f = unpack2(ah[0]); al[0] = pack2(sc[t0][0] - f.x, sc[t0][1] - f.y);
                f = unpack2(ah[1]); al[1] = pack2(sc[t0][2] - f.x, sc[t0][3] - f.y);
                f = unpack2(ah[2]); al[2] = pack2(sc[t1][0] - f.x, sc[t1][1] - f.y);
                f = unpack2(ah[3]); al[3] = pack2(sc[t1][2] - f.x, sc[t1][3] - f.y);
            }
            #pragma unroll
            for (int dtp = 0; dtp < 4; ++dtp) {
                uint32_t vh4[4], vl4[4];
                const int voff = (g * 16 + vRow) * LSTR + dtp * 16 + vColOff;
                LDSM_X4T(vh4, smem_addr(sVh + voff));
                LDSM_X4T(vl4, smem_addr(sVl + voff));
                MMA_BF16(oc[2*dtp],   ah, vh4[0], vh4[1]);
                MMA_BF16(oc[2*dtp],   ah, vl4[0], vl4[1]);
                MMA_BF16(oc[2*dtp],   al, vh4[0], vh4[1]);
                MMA_BF16(oc[2*dtp+1], ah, vh4[2], vh4[3]);
                MMA_BF16(oc[2*dtp+1], ah, vl4[2], vl4[3]);
                MMA_BF16(oc[2*dtp+1], al, vh4[2], vh4[3]);
            }
        }
        __syncthreads();
    }

    // ---- normalize + split-bf16 store ----
    const float inv0 = 1.f / l0;
    const float inv1 = 1.f / l1;
    const int r0 = w * 16 + (lane >> 2);
    const int r1 = r0 + 8;
    const size_t base0 = (size_t)(b * SEQ + qBase + r0) * DIM + h * HDIM;
    const size_t base1 = (size_t)(b * SEQ + qBase + r1) * DIM + h * HDIM;
    #pragma unroll
    for (int dt = 0; dt < 8; ++dt) {
        const int col = dt * 8 + (lane & 3) * 2;
        const float v00 = oc[dt][0] * inv0, v01 = oc[dt][1] * inv0;
        const float v10 = oc[dt][2] * inv1, v11 = oc[dt][3] * inv1;
        uint32_t h0 = pack2(v00, v01);
        float2 f0 = unpack2(h0);
        uint32_t l0w = pack2(v00 - f0.x, v01 - f0.y);
        uint32_t h1 = pack2(v10, v11);
        float2 f1 = unpack2(h1);
        uint32_t l1w = pack2(v10 - f1.x, v11 - f1.y);
        *(uint32_t*)(Oh + base0 + col) = h0;
        *(uint32_t*)(Ol + base0 + col) = l0w;
        *(uint32_t*)(Oh + base1 + col) = h1;
        *(uint32_t*)(Ol + base1 + col) = l1w;
    }
}

// ---------------------------------------------------------------------------
extern "C" void kernel_launch(void* const* d_in, const int* in_sizes, int n_in,
                              void* d_out, int out_size)
{
    const float* x     = (const float*)d_in[0];
    const float* Wq    = (const float*)d_in[1];
    const float* Wkv   = (const float*)d_in[2];
    const float* Wproj = (const float*)d_in[3];
    const float* bproj = (const float*)d_in[4];
    float* out = (float*)d_out;

    bf16 *xh, *xl, *Wqh, *Wql, *Wkh, *Wkl, *Wph, *Wpl;
    bf16 *Qh, *Ql, *KVh, *KVl, *Oh, *Ol;
    cudaGetSymbolAddress((void**)&xh,  g_xh);  cudaGetSymbolAddress((void**)&xl,  g_xl);
    cudaGetSymbolAddress((void**)&Wqh, g_Wqh); cudaGetSymbolAddress((void**)&Wql, g_Wql);
    cudaGetSymbolAddress((void**)&Wkh, g_Wkh); cudaGetSymbolAddress((void**)&Wkl, g_Wkl);
    cudaGetSymbolAddress((void**)&Wph, g_Wph); cudaGetSymbolAddress((void**)&Wpl, g_Wpl);
    cudaGetSymbolAddress((void**)&Qh,  g_Qh);  cudaGetSymbolAddress((void**)&Ql,  g_Ql);
    cudaGetSymbolAddress((void**)&KVh, g_KVh); cudaGetSymbolAddress((void**)&KVl, g_KVl);
    cudaGetSymbolAddress((void**)&Oh,  g_Oh);  cudaGetSymbolAddress((void**)&Ol,  g_Ol);

    static bool attr_set = false;
    if (!attr_set) {
        cudaFuncSetAttribute(attn_mma_kernel,
                             cudaFuncAttributeMaxDynamicSharedMemorySize,
                             ATTN_SMEM_BYTES);
        attr_set = true;
    }

    // 0) fused split conversion
    cvt_all<<<CVT_TOTAL / 256, 256>>>(x, Wq, Wkv, Wproj,
                                      xh, xl, Wqh, Wql, Wkh, Wkl, Wph, Wpl);

    // 1) fused Q|KV projection: N = 768 + 128
    {
        dim3 grid((DIM + KVW) / 128, MROWS / 128);
        gemm_bf16<<<grid, 256>>>(xh, xl,
                                 Wqh, Wql, DIM, Wkh, Wkl, KVW,
                                 MROWS, DIM,
                                 nullptr, nullptr,
                                 Qh, Ql, ATT_SCALE,
                                 KVh, KVl, 1.0f);
    }
    // 2) flash attention
    {
        dim3 grid(SEQ / 128, NHEAD, BATCH);
        attn_mma_kernel<<<grid, 256, ATTN_SMEM_BYTES>>>(Qh, Ql, KVh, KVl, Oh, Ol);
    }
    // 3) out = O @ Wproj + bproj
    {
        dim3 grid(DIM / 128, MROWS / 128);
        gemm_bf16<<<grid, 256>>>(Oh, Ol,
                                 Wph, Wpl, DIM, nullptr, nullptr, 0,
                                 MROWS, DIM,
                                 out, bproj,
                                 nullptr, nullptr, 1.0f,
                                 nullptr, nullptr, 1.0f);
    }
}

// round 13
// speedup vs baseline: 61.6375x; 1.0856x over previous
#include <cuda_runtime.h>
#include <cuda_bf16.h>
#include <math.h>
#include <stdint.h>

#define BATCH 2
#define SEQ   2048
#define DIM   768
#define NHEAD 12
#define HDIM  64
#define KVW   128
#define MROWS (BATCH*SEQ)
#define ATT_SCALE 0.125f

typedef __nv_bfloat16 bf16;

// ---------------- scratch ----------------
__device__ bf16 g_xh [(size_t)MROWS * DIM];
__device__ bf16 g_xl [(size_t)MROWS * DIM];
__device__ bf16 g_Wqh[(size_t)DIM * DIM];
__device__ bf16 g_Wql[(size_t)DIM * DIM];
__device__ bf16 g_Wkh[(size_t)DIM * KVW];
__device__ bf16 g_Wkl[(size_t)DIM * KVW];
__device__ bf16 g_Wph[(size_t)DIM * DIM];
__device__ bf16 g_Wpl[(size_t)DIM * DIM];
__device__ bf16 g_Qh [(size_t)MROWS * DIM];
__device__ bf16 g_Ql [(size_t)MROWS * DIM];
__device__ bf16 g_KVh[(size_t)MROWS * KVW];
__device__ bf16 g_KVl[(size_t)MROWS * KVW];
__device__ bf16 g_Oh [(size_t)MROWS * DIM];
__device__ bf16 g_Ol [(size_t)MROWS * DIM];

// ---------------- helpers ----------------
__device__ __forceinline__ uint32_t pack2(float x, float y) {
    __nv_bfloat162 t = __float22bfloat162_rn(make_float2(x, y));
    return *reinterpret_cast<uint32_t*>(&t);
}
__device__ __forceinline__ float2 unpack2(uint32_t u) {
    __nv_bfloat162 t = *reinterpret_cast<__nv_bfloat162*>(&u);
    return __bfloat1622float2(t);
}
__device__ __forceinline__ uint32_t smem_addr(const void* p) {
    return (uint32_t)__cvta_generic_to_shared(p);
}
__device__ __forceinline__ void cp16(bf16* dst, const bf16* src) {
    asm volatile("cp.async.cg.shared.global [%0], [%1], 16;"
                 :: "r"(smem_addr(dst)), "l"(src));
}
#define CP_COMMIT()  asm volatile("cp.async.commit_group;" ::: "memory")
#define CP_WAIT(n)   asm volatile("cp.async.wait_group " #n ";" ::: "memory")

#define MMA_BF16(c, a, b0, b1)                                                   \
    asm volatile("mma.sync.aligned.m16n8k16.row.col.f32.bf16.bf16.f32 "          \
                 "{%0,%1,%2,%3},{%4,%5,%6,%7},{%8,%9},{%0,%1,%2,%3};"            \
                 : "+f"((c)[0]), "+f"((c)[1]), "+f"((c)[2]), "+f"((c)[3])        \
                 : "r"((a)[0]), "r"((a)[1]), "r"((a)[2]), "r"((a)[3]),           \
                   "r"(b0), "r"(b1))

#define LDSM_X4(r, addr)                                                         \
    asm volatile("ldmatrix.sync.aligned.m8n8.x4.shared.b16 {%0,%1,%2,%3}, [%4];" \
                 : "=r"((r)[0]), "=r"((r)[1]), "=r"((r)[2]), "=r"((r)[3])        \
                 : "r"(addr))
#define LDSM_X4T(r, addr)                                                        \
    asm volatile("ldmatrix.sync.aligned.m8n8.x4.trans.shared.b16 {%0,%1,%2,%3}, [%4];" \
                 : "=r"((r)[0]), "=r"((r)[1]), "=r"((r)[2]), "=r"((r)[3])        \
                 : "r"(addr))
#define LDSM_X2T(r, addr)                                                        \
    asm volatile("ldmatrix.sync.aligned.m8n8.x2.trans.shared.b16 {%0,%1}, [%2];" \
                 : "=r"((r)[0]), "=r"((r)[1]) : "r"(addr))

// ---------------------------------------------------------------------------
// Fused fp32 -> split bf16 for all 4 tensors in one launch.
// ---------------------------------------------------------------------------
#define X4SZ 786432
#define Q4SZ 147456
#define K4SZ 24576
#define CVT_TOTAL (X4SZ + Q4SZ + K4SZ + Q4SZ)

__global__ void cvt_all(const float* __restrict__ x,  const float* __restrict__ Wq,
                        const float* __restrict__ Wkv, const float* __restrict__ Wp,
                        bf16* __restrict__ xh,  bf16* __restrict__ xl,
                        bf16* __restrict__ Wqh, bf16* __restrict__ Wql,
                        bf16* __restrict__ Wkh, bf16* __restrict__ Wkl,
                        bf16* __restrict__ Wph, bf16* __restrict__ Wpl)
{
    int i = blockIdx.x * blockDim.x + threadIdx.x;
    const float* src; bf16 *h, *l; int j = i;
    if (j < X4SZ) { src = x; h = xh; l = xl; }
    else {
        j -= X4SZ;
        if (j < Q4SZ) { src = Wq; h = Wqh; l = Wql; }
        else {
            j -= Q4SZ;
            if (j < K4SZ) { src = Wkv; h = Wkh; l = Wkl; }
            else { j -= K4SZ; src = Wp; h = Wph; l = Wpl; }
        }
    }
    float4 v = ((const float4*)src)[j];
    uint32_t h0 = pack2(v.x, v.y), h1 = pack2(v.z, v.w);
    float2 f0 = unpack2(h0), f1 = unpack2(h1);
    uint32_t l0 = pack2(v.x - f0.x, v.y - f0.y), l1 = pack2(v.z - f1.x, v.w - f1.y);
    ((uint2*)h)[j] = make_uint2(h0, h1);
    ((uint2*)l)[j] = make_uint2(l0, l1);
}

// ---------------------------------------------------------------------------
// Split-bf16 GEMM, cp.async double-buffered, 2 CTAs/SM.
// C[:, 0:N1] = A*B1 ; C[:, N1:N1+N2] = A*B2.
// Stage layout (bf16 elems): sAh@0 (5120), sAl@5120, sBh@10240 (4352), sBl@14592.
// Stage size 18944 elems; 2 stages = 75776 bytes dynamic smem.
// ---------------------------------------------------------------------------
#define ASTR 40
#define BSTR 136
#define G_SAL 5120
#define G_SBH 10240
#define G_SBL 14592
#define G_STG 18944
#define GEMM_SMEM_BYTES (2 * G_STG * 2)

__global__ __launch_bounds__(256, 2)
void gemm_bf16(const bf16* __restrict__ Ah, const bf16* __restrict__ Al,
               const bf16* __restrict__ B1h, const bf16* __restrict__ B1l, int N1,
               const bf16* __restrict__ B2h, const bf16* __restrict__ B2l, int N2,
               int M, int K,
               float* __restrict__ Cf, const float* __restrict__ bias,
               bf16* __restrict__ C1h, bf16* __restrict__ C1l, float scale1,
               bf16* __restrict__ C2h, bf16* __restrict__ C2l, float scale2)
{
    extern __shared__ bf16 gsm[];

    const int tid  = threadIdx.x;
    const int lane = tid & 31;
    const int l16  = lane & 15;
    const int hi8  = (lane >> 4) * 8;
    const int w    = tid >> 5;
    const int wm   = w >> 2;
    const int wn   = w & 3;
    const int rowBlk = blockIdx.y * 128;
    const int colBlk = blockIdx.x * 128;

    const bool isB2 = (colBlk >= N1);
    const bf16* Bh = isB2 ? B2h : B1h;
    const bf16* Bl = isB2 ? B2l : B1l;
    const int   NB = isB2 ? N2 : N1;
    const int   cB = colBlk - (isB2 ? N1 : 0);

    const int aRow = tid >> 2;
    const int aCol = (tid & 3) * 8;
    const int bRow = tid >> 4;
    const int bCol = (tid & 15) * 8;

    auto issue = [&](int kt, bf16* st) {
        const int k0 = kt * 32;
        #pragma unroll
        for (int i = 0; i < 2; ++i) {
            const int ar = aRow + i * 64;
            cp16(st + ar * ASTR + aCol,         Ah + (size_t)(rowBlk + ar) * K + k0 + aCol);
            cp16(st + G_SAL + ar * ASTR + aCol, Al + (size_t)(rowBlk + ar) * K + k0 + aCol);
            const int br = bRow + i * 16;
            cp16(st + G_SBH + br * BSTR + bCol, Bh + (size_t)(k0 + br) * NB + cB + bCol);
            cp16(st + G_SBL + br * BSTR + bCol, Bl + (size_t)(k0 + br) * NB + cB + bCol);
        }
    };

    const int nk = K / 32;
    issue(0, gsm);
    CP_COMMIT();
    if (nk > 1) {
        issue(1, gsm + G_STG);
        CP_COMMIT();
    }

    float acc[4][4][4] = {};

    for (int kt = 0; kt < nk; ++kt) {
        if (kt + 1 < nk) { CP_WAIT(1); } else { CP_WAIT(0); }
        __syncthreads();

        bf16* st = gsm + (kt & 1) * G_STG;
        bf16* sAh = st;
        bf16* sAl = st + G_SAL;
        bf16* sBh = st + G_SBH;
        bf16* sBl = st + G_SBL;

        #pragma unroll
        for (int s = 0; s < 2; ++s) {
            uint32_t bh[4][2], bl[4][2];
            #pragma unroll
            for (int nt = 0; nt < 4; ++nt) {
                const int boff = (s * 16 + l16) * BSTR + wn * 32 + nt * 8;
                LDSM_X2T(bh[nt], smem_addr(sBh + boff));
                LDSM_X2T(bl[nt], smem_addr(sBl + boff));
            }
            #pragma unroll
            for (int mt = 0; mt < 4; ++mt) {
                uint32_t ah[4], al[4];
                const int aoff = (wm * 64 + mt * 16 + l16) * ASTR + s * 16 + hi8;
                LDSM_X4(ah, smem_addr(sAh + aoff));
                LDSM_X4(al, smem_addr(sAl + aoff));
                #pragma unroll
                for (int nt = 0; nt < 4; ++nt) {
                    MMA_BF16(acc[mt][nt], ah, bh[nt][0], bh[nt][1]);
                    MMA_BF16(acc[mt][nt], ah, bl[nt][0], bl[nt][1]);
                    MMA_BF16(acc[mt][nt], al, bh[nt][0], bh[nt][1]);
                }
            }
        }
        __syncthreads();

        if (kt + 2 < nk) {
            issue(kt + 2, st);
            CP_COMMIT();
        }
    }

    bf16* Ch = isB2 ? C2h : C1h;
    bf16* Cl = isB2 ? C2l : C1l;
    const float scale = isB2 ? scale2 : scale1;

    const int rBase = rowBlk + wm * 64 + (lane >> 2);
    const int cLoc  = cB + wn * 32 + (lane & 3) * 2;
    #pragma unroll
    for (int mt = 0; mt < 4; ++mt) {
        const int r0 = rBase + mt * 16;
        const int r1 = r0 + 8;
        #pragma unroll
        for (int nt = 0; nt < 4; ++nt) {
            const int c = cLoc + nt * 8;
            float v00 = acc[mt][nt][0], v01 = acc[mt][nt][1];
            float v10 = acc[mt][nt][2], v11 = acc[mt][nt][3];
            if (Cf) {
                const float b0 = bias ? bias[c] : 0.f;
                const float b1 = bias ? bias[c + 1] : 0.f;
                *(float2*)(Cf + (size_t)r0 * N1 + c) = make_float2(v00 + b0, v01 + b1);
                *(float2*)(Cf + (size_t)r1 * N1 + c) = make_float2(v10 + b0, v11 + b1);
            } else {
                v00 *= scale; v01 *= scale; v10 *= scale; v11 *= scale;
                uint32_t h0 = pack2(v00, v01);
                float2 f0 = unpack2(h0);
                uint32_t l0 = pack2(v00 - f0.x, v01 - f0.y);
                uint32_t h1 = pack2(v10, v11);
                float2 f1 = unpack2(h1);
                uint32_t l1 = pack2(v10 - f1.x, v11 - f1.y);
                *(uint32_t*)(Ch + (size_t)r0 * NB + c) = h0;
                *(uint32_t*)(Cl + (size_t)r0 * NB + c) = l0;
                *(uint32_t*)(Ch + (size_t)r1 * NB + c) = h1;
                *(uint32_t*)(Cl + (size_t)r1 * NB + c) = l1;
            }
        }
    }
}

// ---------------------------------------------------------------------------
// Flash attention: 128q x 64k, 8 warps, cp.async double buffer, x4 ldmatrix.
// ---------------------------------------------------------------------------
#define LSTR 72
#define SQH  0
#define SQL  9216
#define STG0 18432
#define STG_SZ 18432
#define ATTN_SMEM_BYTES (55296 * 2)

__global__ __launch_bounds__(256, 2)
void attn_mma_kernel(const bf16* __restrict__ Qh, const bf16* __restrict__ Ql,
                     const bf16* __restrict__ KVh, const bf16* __restrict__ KVl,
                     bf16* __restrict__ Oh, bf16* __restrict__ Ol)
{
    extern __shared__ bf16 sm[];

    const int tid  = threadIdx.x;
    const int lane = tid & 31;
    const int w    = tid >> 5;
    const int qBase = blockIdx.x * 128;
    const int h     = blockIdx.y;
    const int b     = blockIdx.z;

    const bf16* gkvh = KVh + (size_t)b * SEQ * KVW;
    const bf16* gkvl = KVl + (size_t)b * SEQ * KVW;

    const int kvRow0 = tid >> 3;
    const int kvC    = (tid & 7) * 8;
    auto issue_kv = [&](int kt, bf16* base) {
        #pragma unroll
        for (int j = 0; j < 2; ++j) {
            const int row = kvRow0 + j * 32;
            const size_t g = (size_t)(kt * 64 + row) * KVW + kvC;
            bf16* d = base + row * LSTR + kvC;
            cp16(d,         gkvh + g);
            cp16(d + 4608,  gkvl + g);
            cp16(d + 9216,  gkvh + g + HDIM);
            cp16(d + 13824, gkvl + g + HDIM);
        }
    };

    issue_kv(0, sm + STG0);
    CP_COMMIT();

    {
        const bf16* gqh = Qh + (size_t)(b * SEQ + qBase) * DIM + h * HDIM;
        const bf16* gql = Ql + (size_t)(b * SEQ + qBase) * DIM + h * HDIM;
        #pragma unroll
        for (int j = 0; j < 4; ++j) {
            const int idx = tid + j * 256;
            const int row = idx >> 3;
            const int c   = (idx & 7) * 8;
            *(uint4*)(sm + SQH + row * LSTR + c) = *(const uint4*)(gqh + (size_t)row * DIM + c);
            *(uint4*)(sm + SQL + row * LSTR + c) = *(const uint4*)(gql + (size_t)row * DIM + c);
        }
    }

    float oc[8][4] = {};
    float m0 = -1e30f, m1 = -1e30f, l0 = 0.f, l1 = 0.f;

    const int l16 = lane & 15;
    const int aRow = w * 16 + l16;
    const int aColBase = (lane >> 4) * 8;
    const int kRowOff = (l16 & 7) + ((lane >> 4) << 3);
    const int kColOff = ((l16 >> 3) & 1) * 8;
    const int vRow = l16;
    const int vColOff = (lane >> 4) * 8;

    const int NK = SEQ / 64;
    for (int kt = 0; kt < NK; ++kt) {
        bf16* cur = sm + STG0 + (kt & 1) * STG_SZ;
        if (kt + 1 < NK) {
            issue_kv(kt + 1, sm + STG0 + ((kt + 1) & 1) * STG_SZ);
            CP_COMMIT();
            CP_WAIT(1);
        } else {
            CP_WAIT(0);
        }
        __syncthreads();

        bf16* sKh = cur;
        bf16* sKl = cur + 4608;
        bf16* sVh = cur + 9216;
        bf16* sVl = cur + 13824;

        // ---- S = Q K^T ----
        float sc[8][4] = {};
        #pragma unroll
        for (int ks = 0; ks < 4; ++ks) {
            uint32_t aqh[4], aql[4];
            LDSM_X4(aqh, smem_addr(sm + SQH + aRow * LSTR + ks * 16 + aColBase));
            LDSM_X4(aql, smem_addr(sm + SQL + aRow * LSTR + ks * 16 + aColBase));
            #pragma unroll
            for (int ntp = 0; ntp < 4; ++ntp) {
                uint32_t bkh[4], bkl[4];
                const int boff = (ntp * 16 + kRowOff) * LSTR + ks * 16 + kColOff;
                LDSM_X4(bkh, smem_addr(sKh + boff));
                LDSM_X4(bkl, smem_addr(sKl + boff));
                MMA_BF16(sc[2*ntp],   aqh, bkh[0], bkh[1]);
                MMA_BF16(sc[2*ntp],   aqh, bkl[0], bkl[1]);
                MMA_BF16(sc[2*ntp],   aql, bkh[0], bkh[1]);
                MMA_BF16(sc[2*ntp+1], aqh, bkh[2], bkh[3]);
                MMA_BF16(sc[2*ntp+1], aqh, bkl[2], bkl[3]);
                MMA_BF16(sc[2*ntp+1], aql, bkh[2], bkh[3]);
            }
        }

        // ---- online softmax ----
        float mx0 = -1e30f, mx1 = -1e30f;
        #pragma unroll
        for (int nt = 0; nt < 8; ++nt) {
            mx0 = fmaxf(mx0, fmaxf(sc[nt][0], sc[nt][1]));
            mx1 = fmaxf(mx1, fmaxf(sc[nt][2], sc[nt][3]));
        }
        mx0 = fmaxf(mx0, __shfl_xor_sync(0xffffffffu, mx0, 1));
        mx0 = fmaxf(mx0, __shfl_xor_sync(0xffffffffu, mx0, 2));
        mx1 = fmaxf(mx1, __shfl_xor_sync(0xffffffffu, mx1, 1));
        mx1 = fmaxf(mx1, __shfl_xor_sync(0xffffffffu, mx1, 2));
        const float mn0 = fmaxf(m0, mx0);
        const float mn1 = fmaxf(m1, mx1);
        const float cr0 = __expf(m0 - mn0);
        const float cr1 = __expf(m1 - mn1);
        m0 = mn0; m1 = mn1;

        float s0 = 0.f, s1 = 0.f;
        #pragma unroll
        for (int nt = 0; nt < 8; ++nt) {
            sc[nt][0] = __expf(sc[nt][0] - mn0);
            sc[nt][1] = __expf(sc[nt][1] - mn0);
            sc[nt][2] = __expf(sc[nt][2] - mn1);
            sc[nt][3] = __expf(sc[nt][3] - mn1);
            s0 += sc[nt][0] + sc[nt][1];
            s1 += sc[nt][2] + sc[nt][3];
        }
        s0 += __shfl_xor_sync(0xffffffffu, s0, 1);
        s0 += __shfl_xor_sync(0xffffffffu, s0, 2);
        s1 += __shfl_xor_sync(0xffffffffu, s1, 1);
        s1 += __shfl_xor_sync(0xffffffffu, s1, 2);
        l0 = l0 * cr0 + s0;
        l1 = l1 * cr1 + s1;
        #pragma unroll
        for (int dt = 0; dt < 8; ++dt) {
            oc[dt][0] *= cr0; oc[dt][1] *= cr0;
            oc[dt][2] *= cr1; oc[dt][3] *= cr1;
        }

        // ---- O += P V ----
        #pragma unroll
        for (int g = 0; g < 4; ++g) {
            const int t0 = 2 * g, t1 = 2 * g + 1;
            uint32_t ah[4], al[4];
            ah[0] = pack2(sc[t0][0], sc[t0][1]);
            ah[1] = pack2(sc[t0][2], sc[t0][3]);
            ah[2] = pack2(sc[t1][0], sc[t1][1]);
            ah[3] = pack2(sc[t1][2], sc[t1][3]);
            {
                float2 f;
                f = unpack2(ah[0]); al[0] = pack2(sc[t0][0] - f.x, sc[t0][1] - f.y);
                f = unpack2(ah[1]); al[1] = pack2(sc[t0][2] - f.x, sc[t0][3] - f.y);
                f = unpack2(ah[2]); al[2] = pack2(sc[t1][0] - f.x, sc[t1][1] - f.y);
                f = unpack2(ah[3]); al[3] = pack2(sc[t1][2] - f.x, sc[t1][3] - f.y);
            }
            #pragma unroll
            for (int dtp = 0; dtp < 4; ++dtp) {
                uint32_t vh4[4], vl4[4];
                const int voff = (g * 16 + vRow) * LSTR + dtp * 16 + vColOff;
                LDSM_X4T(vh4, smem_addr(sVh + voff));
                LDSM_X4T(vl4, smem_addr(sVl + voff));
                MMA_BF16(oc[2*dtp],   ah, vh4[0], vh4[1]);
                MMA_BF16(oc[2*dtp],   ah, vl4[0], vl4[1]);
                MMA_BF16(oc[2*dtp],   al, vh4[0], vh4[1]);
                MMA_BF16(oc[2*dtp+1], ah, vh4[2], vh4[3]);
                MMA_BF16(oc[2*dtp+1], ah, vl4[2], vl4[3]);
                MMA_BF16(oc[2*dtp+1], al, vh4[2], vh4[3]);
            }
        }
        __syncthreads();
    }

    // ---- normalize + split-bf16 store ----
    const float inv0 = 1.f / l0;
    const float inv1 = 1.f / l1;
    const int r0 = w * 16 + (lane >> 2);
    const int r1 = r0 + 8;
    const size_t base0 = (size_t)(b * SEQ + qBase + r0) * DIM + h * HDIM;
    const size_t base1 = (size_t)(b * SEQ + qBase + r1) * DIM + h * HDIM;
    #pragma unroll
    for (int dt = 0; dt < 8; ++dt) {
        const int col = dt * 8 + (lane & 3) * 2;
        const float v00 = oc[dt][0] * inv0, v01 = oc[dt][1] * inv0;
        const float v10 = oc[dt][2] * inv1, v11 = oc[dt][3] * inv1;
        uint32_t h0 = pack2(v00, v01);
        float2 f0 = unpack2(h0);
        uint32_t l0w = pack2(v00 - f0.x, v01 - f0.y);
        uint32_t h1 = pack2(v10, v11);
        float2 f1 = unpack2(h1);
        uint32_t l1w = pack2(v10 - f1.x, v11 - f1.y);
        *(uint32_t*)(Oh + base0 + col) = h0;
        *(uint32_t*)(Ol + base0 + col) = l0w;
        *(uint32_t*)(Oh + base1 + col) = h1;
        *(uint32_t*)(Ol + base1 + col) = l1w;
    }
}

// ---------------------------------------------------------------------------
extern "C" void kernel_launch(void* const* d_in, const int* in_sizes, int n_in,
                              void* d_out, int out_size)
{
    const float* x     = (const float*)d_in[0];
    const float* Wq    = (const float*)d_in[1];
    const float* Wkv   = (const float*)d_in[2];
    const float* Wproj = (const float*)d_in[3];
    const float* bproj = (const float*)d_in[4];
    float* out = (float*)d_out;

    bf16 *xh, *xl, *Wqh, *Wql, *Wkh, *Wkl, *Wph, *Wpl;
    bf16 *Qh, *Ql, *KVh, *KVl, *Oh, *Ol;
    cudaGetSymbolAddress((void**)&xh,  g_xh);  cudaGetSymbolAddress((void**)&xl,  g_xl);
    cudaGetSymbolAddress((void**)&Wqh, g_Wqh); cudaGetSymbolAddress((void**)&Wql, g_Wql);
    cudaGetSymbolAddress((void**)&Wkh, g_Wkh); cudaGetSymbolAddress((void**)&Wkl, g_Wkl);
    cudaGetSymbolAddress((void**)&Wph, g_Wph); cudaGetSymbolAddress((void**)&Wpl, g_Wpl);
    cudaGetSymbolAddress((void**)&Qh,  g_Qh);  cudaGetSymbolAddress((void**)&Ql,  g_Ql);
    cudaGetSymbolAddress((void**)&KVh, g_KVh); cudaGetSymbolAddress((void**)&KVl, g_KVl);
    cudaGetSymbolAddress((void**)&Oh,  g_Oh);  cudaGetSymbolAddress((void**)&Ol,  g_Ol);

    static bool attr_set = false;
    if (!attr_set) {
        cudaFuncSetAttribute(attn_mma_kernel,
                             cudaFuncAttributeMaxDynamicSharedMemorySize,
                             ATTN_SMEM_BYTES);
        cudaFuncSetAttribute(gemm_bf16,
                             cudaFuncAttributeMaxDynamicSharedMemorySize,
                             GEMM_SMEM_BYTES);
        attr_set = true;
    }

    // 0) fused split conversion
    cvt_all<<<CVT_TOTAL / 256, 256>>>(x, Wq, Wkv, Wproj,
                                      xh, xl, Wqh, Wql, Wkh, Wkl, Wph, Wpl);

    // 1) fused Q|KV projection: N = 768 + 128
    {
        dim3 grid((DIM + KVW) / 128, MROWS / 128);
        gemm_bf16<<<grid, 256, GEMM_SMEM_BYTES>>>(xh, xl,
                                 Wqh, Wql, DIM, Wkh, Wkl, KVW,
                                 MROWS, DIM,
                                 nullptr, nullptr,
                                 Qh, Ql, ATT_SCALE,
                                 KVh, KVl, 1.0f);
    }
    // 2) flash attention
    {
        dim3 grid(SEQ / 128, NHEAD, BATCH);
        attn_mma_kernel<<<grid, 256, ATTN_SMEM_BYTES>>>(Qh, Ql, KVh, KVl, Oh, Ol);
    }
    // 3) out = O @ Wproj + bproj
    {
        dim3 grid(DIM / 128, MROWS / 128);
        gemm_bf16<<<grid, 256, GEMM_SMEM_BYTES>>>(Oh, Ol,
                                 Wph, Wpl, DIM, nullptr, nullptr, 0,
                                 MROWS, DIM,
                                 out, bproj,
                                 nullptr, nullptr, 1.0f,
                                 nullptr, nullptr, 1.0f);
    }
}

// round 15
// speedup vs baseline: 65.4843x; 1.0624x over previous
#include <cuda_runtime.h>
#include <cuda_bf16.h>
#include <math.h>
#include <stdint.h>

#define BATCH 2
#define SEQ   2048
#define DIM   768
#define NHEAD 12
#define HDIM  64
#define KVW   128
#define MROWS (BATCH*SEQ)
#define ATT_SCALE 0.125f
#define ATT_SCALE_LOG2E 0.1803368801111204f   // 0.125 * log2(e)

typedef __nv_bfloat16 bf16;

// ---------------- scratch ----------------
__device__ bf16 g_xh [(size_t)MROWS * DIM];
__device__ bf16 g_xl [(size_t)MROWS * DIM];
__device__ bf16 g_Wqh[(size_t)DIM * DIM];
__device__ bf16 g_Wql[(size_t)DIM * DIM];
__device__ bf16 g_Wkh[(size_t)DIM * KVW];
__device__ bf16 g_Wkl[(size_t)DIM * KVW];
__device__ bf16 g_Wph[(size_t)DIM * DIM];
__device__ bf16 g_Wpl[(size_t)DIM * DIM];
__device__ bf16 g_Qh [(size_t)MROWS * DIM];
__device__ bf16 g_Ql [(size_t)MROWS * DIM];
__device__ bf16 g_KVh[(size_t)MROWS * KVW];
__device__ bf16 g_KVl[(size_t)MROWS * KVW];
__device__ bf16 g_Oh [(size_t)MROWS * DIM];
__device__ bf16 g_Ol [(size_t)MROWS * DIM];

// ---------------- helpers ----------------
__device__ __forceinline__ uint32_t pack2(float x, float y) {
    __nv_bfloat162 t = __float22bfloat162_rn(make_float2(x, y));
    return *reinterpret_cast<uint32_t*>(&t);
}
__device__ __forceinline__ float2 unpack2(uint32_t u) {
    __nv_bfloat162 t = *reinterpret_cast<__nv_bfloat162*>(&u);
    return __bfloat1622float2(t);
}
__device__ __forceinline__ uint32_t smem_addr(const void* p) {
    return (uint32_t)__cvta_generic_to_shared(p);
}
__device__ __forceinline__ void cp16(bf16* dst, const bf16* src) {
    asm volatile("cp.async.cg.shared.global [%0], [%1], 16;"
                 :: "r"(smem_addr(dst)), "l"(src));
}
#define CP_COMMIT()  asm volatile("cp.async.commit_group;" ::: "memory")
#define CP_WAIT(n)   asm volatile("cp.async.wait_group " #n ";" ::: "memory")

#define MMA_BF16(c, a, b0, b1)                                                   \
    asm volatile("mma.sync.aligned.m16n8k16.row.col.f32.bf16.bf16.f32 "          \
                 "{%0,%1,%2,%3},{%4,%5,%6,%7},{%8,%9},{%0,%1,%2,%3};"            \
                 : "+f"((c)[0]), "+f"((c)[1]), "+f"((c)[2]), "+f"((c)[3])        \
                 : "r"((a)[0]), "r"((a)[1]), "r"((a)[2]), "r"((a)[3]),           \
                   "r"(b0), "r"(b1))

#define LDSM_X4(r, addr)                                                         \
    asm volatile("ldmatrix.sync.aligned.m8n8.x4.shared.b16 {%0,%1,%2,%3}, [%4];" \
                 : "=r"((r)[0]), "=r"((r)[1]), "=r"((r)[2]), "=r"((r)[3])        \
                 : "r"(addr))
#define LDSM_X4T(r, addr)                                                        \
    asm volatile("ldmatrix.sync.aligned.m8n8.x4.trans.shared.b16 {%0,%1,%2,%3}, [%4];" \
                 : "=r"((r)[0]), "=r"((r)[1]), "=r"((r)[2]), "=r"((r)[3])        \
                 : "r"(addr))
#define LDSM_X2T(r, addr)                                                        \
    asm volatile("ldmatrix.sync.aligned.m8n8.x2.trans.shared.b16 {%0,%1}, [%2];" \
                 : "=r"((r)[0]), "=r"((r)[1]) : "r"(addr))

// ---------------------------------------------------------------------------
// Fused fp32 -> split bf16 for all 4 tensors in one launch.
// ---------------------------------------------------------------------------
#define X4SZ 786432
#define Q4SZ 147456
#define K4SZ 24576
#define CVT_TOTAL (X4SZ + Q4SZ + K4SZ + Q4SZ)

__global__ void cvt_all(const float* __restrict__ x,  const float* __restrict__ Wq,
                        const float* __restrict__ Wkv, const float* __restrict__ Wp,
                        bf16* __restrict__ xh,  bf16* __restrict__ xl,
                        bf16* __restrict__ Wqh, bf16* __restrict__ Wql,
                        bf16* __restrict__ Wkh, bf16* __restrict__ Wkl,
                        bf16* __restrict__ Wph, bf16* __restrict__ Wpl)
{
    int i = blockIdx.x * blockDim.x + threadIdx.x;
    const float* src; bf16 *h, *l; int j = i;
    if (j < X4SZ) { src = x; h = xh; l = xl; }
    else {
        j -= X4SZ;
        if (j < Q4SZ) { src = Wq; h = Wqh; l = Wql; }
        else {
            j -= Q4SZ;
            if (j < K4SZ) { src = Wkv; h = Wkh; l = Wkl; }
            else { j -= K4SZ; src = Wp; h = Wph; l = Wpl; }
        }
    }
    float4 v = ((const float4*)src)[j];
    uint32_t h0 = pack2(v.x, v.y), h1 = pack2(v.z, v.w);
    float2 f0 = unpack2(h0), f1 = unpack2(h1);
    uint32_t l0 = pack2(v.x - f0.x, v.y - f0.y), l1 = pack2(v.z - f1.x, v.w - f1.y);
    ((uint2*)h)[j] = make_uint2(h0, h1);
    ((uint2*)l)[j] = make_uint2(l0, l1);
}

// ---------------------------------------------------------------------------
// Split-bf16 GEMM, 128x64 block tile, BK=32, cp.async double buffer, 3 CTAs/SM.
// 8 warps as 4(m) x 2(n); each warp 32x32 (2 m16-tiles x 4 n8-tiles).
// Stage (bf16 elems): sAh@0 (5120), sAl@5120 (5120), sBh@10240 (2304), sBl@12544 (2304).
// Stage = 14848 elems; 2 stages = 59392 bytes dynamic smem.
// ---------------------------------------------------------------------------
#define ASTR 40
#define BSTR 72
#define G_SAL 5120
#define G_SBH 10240
#define G_SBL 12544
#define G_STG 14848
#define GEMM_SMEM_BYTES (2 * G_STG * 2)

__global__ __launch_bounds__(256, 3)
void gemm_bf16(const bf16* __restrict__ Ah, const bf16* __restrict__ Al,
               const bf16* __restrict__ B1h, const bf16* __restrict__ B1l, int N1,
               const bf16* __restrict__ B2h, const bf16* __restrict__ B2l, int N2,
               int M, int K,
               float* __restrict__ Cf, const float* __restrict__ bias,
               bf16* __restrict__ C1h, bf16* __restrict__ C1l, float scale1,
               bf16* __restrict__ C2h, bf16* __restrict__ C2l, float scale2)
{
    extern __shared__ bf16 gsm[];

    const int tid  = threadIdx.x;
    const int lane = tid & 31;
    const int l16  = lane & 15;
    const int hi8  = (lane >> 4) * 8;
    const int w    = tid >> 5;
    const int wm   = w >> 1;        // 0..3 (32 rows each)
    const int wn   = w & 1;         // 0..1 (32 cols each)
    const int rowBlk = blockIdx.y * 128;
    const int colBlk = blockIdx.x * 64;

    const bool isB2 = (colBlk >= N1);
    const bf16* Bh = isB2 ? B2h : B1h;
    const bf16* Bl = isB2 ? B2l : B1l;
    const int   NB = isB2 ? N2 : N1;
    const int   cB = colBlk - (isB2 ? N1 : 0);

    // A loader: 128 rows x 32 cols, 4 cp16/thread
    const int aRow = tid >> 2;            // 0..63 (+64)
    const int aCol = (tid & 3) * 8;
    // B loader: 32 rows x 64 cols, 2 cp16/thread
    const int bRow = tid >> 3;            // 0..31
    const int bCol = (tid & 7) * 8;

    auto issue = [&](int kt, bf16* st) {
        const int k0 = kt * 32;
        #pragma unroll
        for (int i = 0; i < 2; ++i) {
            const int ar = aRow + i * 64;
            cp16(st + ar * ASTR + aCol,         Ah + (size_t)(rowBlk + ar) * K + k0 + aCol);
            cp16(st + G_SAL + ar * ASTR + aCol, Al + (size_t)(rowBlk + ar) * K + k0 + aCol);
        }
        cp16(st + G_SBH + bRow * BSTR + bCol, Bh + (size_t)(k0 + bRow) * NB + cB + bCol);
        cp16(st + G_SBL + bRow * BSTR + bCol, Bl + (size_t)(k0 + bRow) * NB + cB + bCol);
    };

    const int nk = K / 32;
    issue(0, gsm);
    CP_COMMIT();
    if (nk > 1) {
        issue(1, gsm + G_STG);
        CP_COMMIT();
    }

    float acc[2][4][4] = {};

    for (int kt = 0; kt < nk; ++kt) {
        if (kt + 1 < nk) { CP_WAIT(1); } else { CP_WAIT(0); }
        __syncthreads();

        bf16* st  = gsm + (kt & 1) * G_STG;
        bf16* sAh = st;
        bf16* sAl = st + G_SAL;
        bf16* sBh = st + G_SBH;
        bf16* sBl = st + G_SBL;

        #pragma unroll
        for (int s = 0; s < 2; ++s) {
            uint32_t bh[4][2], bl[4][2];
            #pragma unroll
            for (int nt = 0; nt < 4; ++nt) {
                const int boff = (s * 16 + l16) * BSTR + wn * 32 + nt * 8;
                LDSM_X2T(bh[nt], smem_addr(sBh + boff));
                LDSM_X2T(bl[nt], smem_addr(sBl + boff));
            }
            #pragma unroll
            for (int mt = 0; mt < 2; ++mt) {
                uint32_t ah[4], al[4];
                const int aoff = (wm * 32 + mt * 16 + l16) * ASTR + s * 16 + hi8;
                LDSM_X4(ah, smem_addr(sAh + aoff));
                LDSM_X4(al, smem_addr(sAl + aoff));
                #pragma unroll
                for (int nt = 0; nt < 4; ++nt) {
                    MMA_BF16(acc[mt][nt], ah, bh[nt][0], bh[nt][1]);
                    MMA_BF16(acc[mt][nt], ah, bl[nt][0], bl[nt][1]);
                    MMA_BF16(acc[mt][nt], al, bh[nt][0], bh[nt][1]);
                }
            }
        }
        __syncthreads();

        if (kt + 2 < nk) {
            issue(kt + 2, st);
            CP_COMMIT();
        }
    }

    bf16* Ch = isB2 ? C2h : C1h;
    bf16* Cl = isB2 ? C2l : C1l;
    const float scale = isB2 ? scale2 : scale1;

    const int rBase = rowBlk + wm * 32 + (lane >> 2);
    const int cLoc  = cB + wn * 32 + (lane & 3) * 2;
    #pragma unroll
    for (int mt = 0; mt < 2; ++mt) {
        const int r0 = rBase + mt * 16;
        const int r1 = r0 + 8;
        #pragma unroll
        for (int nt = 0; nt < 4; ++nt) {
            const int c = cLoc + nt * 8;
            float v00 = acc[mt][nt][0], v01 = acc[mt][nt][1];
            float v10 = acc[mt][nt][2], v11 = acc[mt][nt][3];
            if (Cf) {
                const float b0 = bias ? bias[c] : 0.f;
                const float b1 = bias ? bias[c + 1] : 0.f;
                *(float2*)(Cf + (size_t)r0 * N1 + c) = make_float2(v00 + b0, v01 + b1);
                *(float2*)(Cf + (size_t)r1 * N1 + c) = make_float2(v10 + b0, v11 + b1);
            } else {
                v00 *= scale; v01 *= scale; v10 *= scale; v11 *= scale;
                uint32_t h0 = pack2(v00, v01);
                float2 f0 = unpack2(h0);
                uint32_t l0 = pack2(v00 - f0.x, v01 - f0.y);
                uint32_t h1 = pack2(v10, v11);
                float2 f1 = unpack2(h1);
                uint32_t l1 = pack2(v10 - f1.x, v11 - f1.y);
                *(uint32_t*)(Ch + (size_t)r0 * NB + c) = h0;
                *(uint32_t*)(Cl + (size_t)r0 * NB + c) = l0;
                *(uint32_t*)(Ch + (size_t)r1 * NB + c) = h1;
                *(uint32_t*)(Cl + (size_t)r1 * NB + c) = l1;
            }
        }
    }
}

// ---------------------------------------------------------------------------
// Flash attention: 128q x 64k, 8 warps, cp.async double buffer, x4 ldmatrix.
// Q pre-scaled by 0.125*log2(e); softmax in base 2 (exp2f).
// ---------------------------------------------------------------------------
#define LSTR 72
#define SQH  0
#define SQL  9216
#define STG0 18432
#define STG_SZ 18432
#define ATTN_SMEM_BYTES (55296 * 2)

__global__ __launch_bounds__(256, 2)
void attn_mma_kernel(const bf16* __restrict__ Qh, const bf16* __restrict__ Ql,
                     const bf16* __restrict__ KVh, const bf16* __restrict__ KVl,
                     bf16* __restrict__ Oh, bf16* __restrict__ Ol)
{
    extern __shared__ bf16 sm[];

    const int tid  = threadIdx.x;
    const int lane = tid & 31;
    const int w    = tid >> 5;
    const int qBase = blockIdx.x * 128;
    const int h     = blockIdx.y;
    const int b     = blockIdx.z;

    const bf16* gkvh = KVh + (size_t)b * SEQ * KVW;
    const bf16* gkvl = KVl + (size_t)b * SEQ * KVW;

    const int kvRow0 = tid >> 3;
    const int kvC    = (tid & 7) * 8;
    auto issue_kv = [&](int kt, bf16* base) {
        #pragma unroll
        for (int j = 0; j < 2; ++j) {
            const int row = kvRow0 + j * 32;
            const size_t g = (size_t)(kt * 64 + row) * KVW + kvC;
            bf16* d = base + row * LSTR + kvC;
            cp16(d,         gkvh + g);
            cp16(d + 4608,  gkvl + g);
            cp16(d + 9216,  gkvh + g + HDIM);
            cp16(d + 13824, gkvl + g + HDIM);
        }
    };

    issue_kv(0, sm + STG0);
    CP_COMMIT();

    {
        const bf16* gqh = Qh + (size_t)(b * SEQ + qBase) * DIM + h * HDIM;
        const bf16* gql = Ql + (size_t)(b * SEQ + qBase) * DIM + h * HDIM;
        #pragma unroll
        for (int j = 0; j < 4; ++j) {
            const int idx = tid + j * 256;
            const int row = idx >> 3;
            const int c   = (idx & 7) * 8;
            *(uint4*)(sm + SQH + row * LSTR + c) = *(const uint4*)(gqh + (size_t)row * DIM + c);
            *(uint4*)(sm + SQL + row * LSTR + c) = *(const uint4*)(gql + (size_t)row * DIM + c);
        }
    }

    float oc[8][4] = {};
    float m0 = -1e30f, m1 = -1e30f, l0 = 0.f, l1 = 0.f;

    const int l16 = lane & 15;
    const int aRow = w * 16 + l16;
    const int aColBase = (lane >> 4) * 8;
    const int kRowOff = (l16 & 7) + ((lane >> 4) << 3);
    const int kColOff = ((l16 >> 3) & 1) * 8;
    const int vRow = l16;
    const int vColOff = (lane >> 4) * 8;

    const int NK = SEQ / 64;
    for (int kt = 0; kt < NK; ++kt) {
        bf16* cur = sm + STG0 + (kt & 1) * STG_SZ;
        if (kt + 1 < NK) {
            issue_kv(kt + 1, sm + STG0 + ((kt + 1) & 1) * STG_SZ);
            CP_COMMIT();
            CP_WAIT(1);
        } else {
            CP_WAIT(0);
        }
        __syncthreads();

        bf16* sKh = cur;
        bf16* sKl = cur + 4608;
        bf16* sVh = cur + 9216;
        bf16* sVl = cur + 13824;

        // ---- S = Q K^T (logits in log2 units) ----
        float sc[8][4] = {};
        #pragma unroll
        for (int ks = 0; ks < 4; ++ks) {
            uint32_t aqh[4], aql[4];
            LDSM_X4(aqh, smem_addr(sm + SQH + aRow * LSTR + ks * 16 + aColBase));
            LDSM_X4(aql, smem_addr(sm + SQL + aRow * LSTR + ks * 16 + aColBase));
            #pragma unroll
            for (int ntp = 0; ntp < 4; ++ntp) {
                uint32_t bkh[4], bkl[4];
                const int boff = (ntp * 16 + kRowOff) * LSTR + ks * 16 + kColOff;
                LDSM_X4(bkh, smem_addr(sKh + boff));
                LDSM_X4(bkl, smem_addr(sKl + boff));
                MMA_BF16(sc[2*ntp],   aqh, bkh[0], bkh[1]);
                MMA_BF16(sc[2*ntp],   aqh, bkl[0], bkl[1]);
                MMA_BF16(sc[2*ntp],   aql, bkh[0], bkh[1]);
                MMA_BF16(sc[2*ntp+1], aqh, bkh[2], bkh[3]);
                MMA_BF16(sc[2*ntp+1], aqh, bkl[2], bkl[3]);
                MMA_BF16(sc[2*ntp+1], aql, bkh[2], bkh[3]);
            }
        }

        // ---- online softmax (base 2) ----
        float mx0 = -1e30f, mx1 = -1e30f;
        #pragma unroll
        for (int nt = 0; nt < 8; ++nt) {
            mx0 = fmaxf(mx0, fmaxf(sc[nt][0], sc[nt][1]));
            mx1 = fmaxf(mx1, fmaxf(sc[nt][2], sc[nt][3]));
        }
        mx0 = fmaxf(mx0, __shfl_xor_sync(0xffffffffu, mx0, 1));
        mx0 = fmaxf(mx0, __shfl_xor_sync(0xffffffffu, mx0, 2));
        mx1 = fmaxf(mx1, __shfl_xor_sync(0xffffffffu, mx1, 1));
        mx1 = fmaxf(mx1, __shfl_xor_sync(0xffffffffu, mx1, 2));
        const float mn0 = fmaxf(m0, mx0);
        const float mn1 = fmaxf(m1, mx1);
        const float cr0 = exp2f(m0 - mn0);
        const float cr1 = exp2f(m1 - mn1);
        m0 = mn0; m1 = mn1;

        float s0 = 0.f, s1 = 0.f;
        #pragma unroll
        for (int nt = 0; nt < 8; ++nt) {
            sc[nt][0] = exp2f(sc[nt][0] - mn0);
            sc[nt][1] = exp2f(sc[nt][1] - mn0);
            sc[nt][2] = exp2f(sc[nt][2] - mn1);
            sc[nt][3] = exp2f(sc[nt][3] - mn1);
            s0 += sc[nt][0] + sc[nt][1];
            s1 += sc[nt][2] + sc[nt][3];
        }
        s0 += __shfl_xor_sync(0xffffffffu, s0, 1);
        s0 += __shfl_xor_sync(0xffffffffu, s0, 2);
        s1 += __shfl_xor_sync(0xffffffffu, s1, 1);
        s1 += __shfl_xor_sync(0xffffffffu, s1, 2);
        l0 = l0 * cr0 + s0;
        l1 = l1 * cr1 + s1;
        #pragma unroll
        for (int dt = 0; dt < 8; ++dt) {
            oc[dt][0] *= cr0; oc[dt][1] *= cr0;
            oc[dt][2] *= cr1; oc[dt][3] *= cr1;
        }

        // ---- O += P V ----
        #pragma unroll
        for (int g = 0; g < 4; ++g) {
            const int t0 = 2 * g, t1 = 2 * g + 1;
            uint32_t ah[4], al[4];
            ah[0] = pack2(sc[t0][0], sc[t0][1]);
            ah[1] = pack2(sc[t0][2], sc[t0][3]);
            ah[2] = pack2(sc[t1][0], sc[t1][1]);
            ah[3] = pack2(sc[t1][2], sc[t1][3]);
            {
                float2 f;
                f = unpack2(ah[0]); al[0] = pack2(sc[t0][0] - f.x, sc[t0][1] - f.y);
                f = unpack2(ah[1]); al[1] = pack2(sc[t0][2] - f.x, sc[t0][3] - f.y);
                f = unpack2(ah[2]); al[2] = pack2(sc[t1][0] - f.x, sc[t1][1] - f.y);
                f = unpack2(ah[3]); al[3] = pack2(sc[t1][2] - f.x, sc[t1][3] - f.y);
            }
            #pragma unroll
            for (int dtp = 0; dtp < 4; ++dtp) {
                uint32_t vh4[4], vl4[4];
                const int voff = (g * 16 + vRow) * LSTR + dtp * 16 + vColOff;
                LDSM_X4T(vh4, smem_addr(sVh + voff));
                LDSM_X4T(vl4, smem_addr(sVl + voff));
                MMA_BF16(oc[2*dtp],   ah, vh4[0], vh4[1]);
                MMA_BF16(oc[2*dtp],   ah, vl4[0], vl4[1]);
                MMA_BF16(oc[2*dtp],   al, vh4[0], vh4[1]);
                MMA_BF16(oc[2*dtp+1], ah, vh4[2], vh4[3]);
                MMA_BF16(oc[2*dtp+1], ah, vl4[2], vl4[3]);
                MMA_BF16(oc[2*dtp+1], al, vh4[2], vh4[3]);
            }
        }
        __syncthreads();
    }

    // ---- normalize + split-bf16 store ----
    const float inv0 = 1.f / l0;
    const float inv1 = 1.f / l1;
    const int r0 = w * 16 + (lane >> 2);
    const int r1 = r0 + 8;
    const size_t base0 = (size_t)(b * SEQ + qBase + r0) * DIM + h * HDIM;
    const size_t base1 = (size_t)(b * SEQ + qBase + r1) * DIM + h * HDIM;
    #pragma unroll
    for (int dt = 0; dt < 8; ++dt) {
        const int col = dt * 8 + (lane & 3) * 2;
        const float v00 = oc[dt][0] * inv0, v01 = oc[dt][1] * inv0;
        const float v10 = oc[dt][2] * inv1, v11 = oc[dt][3] * inv1;
        uint32_t h0 = pack2(v00, v01);
        float2 f0 = unpack2(h0);
        uint32_t l0w = pack2(v00 - f0.x, v01 - f0.y);
        uint32_t h1 = pack2(v10, v11);
        float2 f1 = unpack2(h1);
        uint32_t l1w = pack2(v10 - f1.x, v11 - f1.y);
        *(uint32_t*)(Oh + base0 + col) = h0;
        *(uint32_t*)(Ol + base0 + col) = l0w;
        *(uint32_t*)(Oh + base1 + col) = h1;
        *(uint32_t*)(Ol + base1 + col) = l1w;
    }
}

// ---------------------------------------------------------------------------
extern "C" void kernel_launch(void* const* d_in, const int* in_sizes, int n_in,
                              void* d_out, int out_size)
{
    const float* x     = (const float*)d_in[0];
    const float* Wq    = (const float*)d_in[1];
    const float* Wkv   = (const float*)d_in[2];
    const float* Wproj = (const float*)d_in[3];
    const float* bproj = (const float*)d_in[4];
    float* out = (float*)d_out;

    bf16 *xh, *xl, *Wqh, *Wql, *Wkh, *Wkl, *Wph, *Wpl;
    bf16 *Qh, *Ql, *KVh, *KVl, *Oh, *Ol;
    cudaGetSymbolAddress((void**)&xh,  g_xh);  cudaGetSymbolAddress((void**)&xl,  g_xl);
    cudaGetSymbolAddress((void**)&Wqh, g_Wqh); cudaGetSymbolAddress((void**)&Wql, g_Wql);
    cudaGetSymbolAddress((void**)&Wkh, g_Wkh); cudaGetSymbolAddress((void**)&Wkl, g_Wkl);
    cudaGetSymbolAddress((void**)&Wph, g_Wph); cudaGetSymbolAddress((void**)&Wpl, g_Wpl);
    cudaGetSymbolAddress((void**)&Qh,  g_Qh);  cudaGetSymbolAddress((void**)&Ql,  g_Ql);
    cudaGetSymbolAddress((void**)&KVh, g_KVh); cudaGetSymbolAddress((void**)&KVl, g_KVl);
    cudaGetSymbolAddress((void**)&Oh,  g_Oh);  cudaGetSymbolAddress((void**)&Ol,  g_Ol);

    static bool attr_set = false;
    if (!attr_set) {
        cudaFuncSetAttribute(attn_mma_kernel,
                             cudaFuncAttributeMaxDynamicSharedMemorySize,
                             ATTN_SMEM_BYTES);
        cudaFuncSetAttribute(gemm_bf16,
                             cudaFuncAttributeMaxDynamicSharedMemorySize,
                             GEMM_SMEM_BYTES);
        attr_set = true;
    }

    // 0) fused split conversion
    cvt_all<<<CVT_TOTAL / 256, 256>>>(x, Wq, Wkv, Wproj,
                                      xh, xl, Wqh, Wql, Wkh, Wkl, Wph, Wpl);

    // 1) fused Q|KV projection: N = 768 + 128, Q scaled by 0.125*log2(e)
    {
        dim3 grid((DIM + KVW) / 64, MROWS / 128);
        gemm_bf16<<<grid, 256, GEMM_SMEM_BYTES>>>(xh, xl,
                                 Wqh, Wql, DIM, Wkh, Wkl, KVW,
                                 MROWS, DIM,
                                 nullptr, nullptr,
                                 Qh, Ql, ATT_SCALE_LOG2E,
                                 KVh, KVl, 1.0f);
    }
    // 2) flash attention (base-2 softmax)
    {
        dim3 grid(SEQ / 128, NHEAD, BATCH);
        attn_mma_kernel<<<grid, 256, ATTN_SMEM_BYTES>>>(Qh, Ql, KVh, KVl, Oh, Ol);
    }
    // 3) out = O @ Wproj + bproj
    {
        dim3 grid(DIM / 64, MROWS / 128);
        gemm_bf16<<<grid, 256, GEMM_SMEM_BYTES>>>(Oh, Ol,
                                 Wph, Wpl, DIM, nullptr, nullptr, 0,
                                 MROWS, DIM,
                                 out, bproj,
                                 nullptr, nullptr, 1.0f,
                                 nullptr, nullptr, 1.0f);
    }
}